// round 13
// baseline (speedup 1.0000x reference)
#include <cuda_runtime.h>
#include <math.h>
#include <stdint.h>

#define NB 2
#define NL 2048
#define ND 1024
#define NH 16
#define NDH 64
#define MROWS (NB*NL)   // 4096
#define HID (4*ND)      // 4096

// ---------------- scratch ----------------
__device__ float g_h  [(size_t)MROWS * HID];
__device__ float g_q  [(size_t)NB*NH*NL*NDH];
__device__ float g_k  [(size_t)NB*NH*NL*NDH];
__device__ float g_v  [(size_t)NB*NH*NL*NDH];
__device__ float g_ym [(size_t)MROWS * ND];
__device__ float g_z  [(size_t)MROWS * ND];
__device__ float g_pos[NB*NL];
__device__ float g_xr [(size_t)MROWS * ND];   // tf32-rounded x
__device__ float g_pwr[(size_t)HID * ND];     // tf32-rounded proj_w
__device__ float g_owr[(size_t)ND * ND];      // tf32-rounded out_w

// fast silu: x * rcp(1+exp(-x)); ~4 instrs, rel err ~1e-6 (negligible vs tf32)
__device__ __forceinline__ float silu_f(float x){
    return __fdividef(x, 1.0f + __expf(-x));
}

__device__ __forceinline__ uint32_t tf32_bits(float x){
    uint32_t u; asm("cvt.rna.tf32.f32 %0, %1;" : "=r"(u) : "f"(x));
    return u;
}
__device__ __forceinline__ float tf32_rnd(float x){ return __uint_as_float(tf32_bits(x)); }

__device__ __forceinline__ uint32_t smem_u32(const void* p){
    uint32_t a;
    asm("{ .reg .u64 t; cvta.to.shared.u64 t, %1; cvt.u32.u64 %0, t; }" : "=r"(a) : "l"(p));
    return a;
}
__device__ __forceinline__ void cp_async16(uint32_t saddr, const void* g){
    asm volatile("cp.async.cg.shared.global [%0], [%1], 16;" :: "r"(saddr), "l"(g));
}
#define CP_COMMIT()  asm volatile("cp.async.commit_group;" ::: "memory")
#define CP_WAIT(n)   asm volatile("cp.async.wait_group %0;" :: "n"(n) : "memory")

#define MMA16N8K8(c, a, b) \
    asm volatile("mma.sync.aligned.m16n8k8.row.col.f32.tf32.tf32.f32 " \
        "{%0,%1,%2,%3}, {%4,%5,%6,%7}, {%8,%9}, {%0,%1,%2,%3};" \
        : "+f"((c)[0]), "+f"((c)[1]), "+f"((c)[2]), "+f"((c)[3]) \
        : "r"((a)[0]), "r"((a)[1]), "r"((a)[2]), "r"((a)[3]), \
          "r"((b)[0]), "r"((b)[1]))

// ---------------- 0. tf32 pre-round ----------------
__global__ void round_tf32_kernel(const float* __restrict__ in, float* __restrict__ out, int n4)
{
    int i = blockIdx.x * blockDim.x + threadIdx.x;
    if (i < n4){
        float4 v = ((const float4*)in)[i];
        v.x = tf32_rnd(v.x); v.y = tf32_rnd(v.y);
        v.z = tf32_rnd(v.z); v.w = tf32_rnd(v.w);
        ((float4*)out)[i] = v;
    }
}

// ---------------- 1. cumsum of rope_lambda -> g_pos ----------------
__global__ void cumsum_kernel(const float* __restrict__ rl)
{
    __shared__ float s[1024];
    int b = blockIdx.x, t = threadIdx.x;
    const float* a = rl + (size_t)b * NL;
    float x0 = a[2*t], x1 = a[2*t+1];
    float sum = x0 + x1;
    s[t] = sum;
    __syncthreads();
    for (int off = 1; off < 1024; off <<= 1){
        float v = (t >= off) ? s[t-off] : 0.0f;
        __syncthreads();
        s[t] += v;
        __syncthreads();
    }
    float incl = s[t];
    g_pos[b*NL + 2*t]     = incl - x1;
    g_pos[b*NL + 2*t + 1] = incl;
}

// ---------------- 2/5. tf32 mma.sync GEMM (NT), 3-stage; operands PRE-ROUNDED ----------------
#define GSTAGES 3
#define GKC 32
#define G_STRIDE 36
#define G_TILE_F (128*G_STRIDE)
#define G_TILE_B (G_TILE_F*4)
#define G_SMEM_BYTES (GSTAGES * 2 * G_TILE_B)   // 110592

template<int EPI>
__global__ void __launch_bounds__(256, 2)
gemm_mma(const float* __restrict__ A, const float* __restrict__ Bw,
         const float* __restrict__ bias, const float* __restrict__ resid,
         float* __restrict__ C, int N, int K)
{
    extern __shared__ float dsm[];
    const uint32_t sb = smem_u32(dsm);
    const int tid  = threadIdx.x;
    const int lane = tid & 31, wid = tid >> 5;
    const int wm = wid >> 2, wn = wid & 3;
    const int g  = lane >> 2, t = lane & 3;
    const int bn = blockIdx.x * 128;
    const int bm = blockIdx.y * 128;

    float acc[4][4][4];
    #pragma unroll
    for (int i = 0; i < 4; i++)
        #pragma unroll
        for (int j = 0; j < 4; j++)
            #pragma unroll
            for (int c = 0; c < 4; c++) acc[i][j][c] = 0.0f;

    auto load_stage = [&](int s, int kt){
        uint32_t base = sb + (uint32_t)s * (2*G_TILE_B);
        #pragma unroll
        for (int it = 0; it < 8; it++){
            int idx = tid + it*256;
            int isB = idx >> 10;
            int li  = idx & 1023;
            int row = li >> 3;
            int c16 = li & 7;
            const float* src = (isB ? (Bw + (size_t)(bn+row)*K)
                                    : (A  + (size_t)(bm+row)*K)) + kt + c16*4;
            cp_async16(base + (uint32_t)isB*G_TILE_B + (uint32_t)(row*144 + c16*16), src);
        }
        CP_COMMIT();
    };

    #pragma unroll
    for (int s = 0; s < GSTAGES; s++) load_stage(s, s*GKC);

    const int NCH = K / GKC;
    int s = 0;
    for (int ch = 0; ch < NCH; ch++){
        CP_WAIT(GSTAGES-1);
        __syncthreads();

        const float* As = dsm + (size_t)s*2*G_TILE_F;
        const float* Bs = As + G_TILE_F;
        const float* Awp = As + (wm*64 + g)*G_STRIDE + t;
        const float* Bwp = Bs + (wn*32 + g)*G_STRIDE + t;

        #pragma unroll
        for (int ks = 0; ks < 4; ks++){
            int k0 = ks*8;
            uint32_t b[4][2];
            #pragma unroll
            for (int fj = 0; fj < 4; fj++){
                const float* bp = Bwp + fj*8*G_STRIDE + k0;
                b[fj][0] = __float_as_uint(bp[0]);
                b[fj][1] = __float_as_uint(bp[4]);
            }
            #pragma unroll
            for (int fi = 0; fi < 4; fi++){
                const float* ap = Awp + fi*16*G_STRIDE + k0;
                uint32_t a[4];
                a[0] = __float_as_uint(ap[0]);
                a[1] = __float_as_uint(ap[8*G_STRIDE]);
                a[2] = __float_as_uint(ap[4]);
                a[3] = __float_as_uint(ap[8*G_STRIDE+4]);
                #pragma unroll
                for (int fj = 0; fj < 4; fj++)
                    MMA16N8K8(acc[fi][fj], a, b[fj]);
            }
        }
        __syncthreads();
        if (ch + GSTAGES < NCH) load_stage(s, (ch + GSTAGES)*GKC);
        if (++s == GSTAGES) s = 0;
    }

    #pragma unroll
    for (int fi = 0; fi < 4; fi++){
        int m0 = bm + wm*64 + fi*16 + g;
        #pragma unroll
        for (int fj = 0; fj < 4; fj++){
            int n = bn + wn*32 + fj*8 + 2*t;
            float2 bv = *(const float2*)(bias + n);
            float2 o0, o1;
            o0.x = acc[fi][fj][0] + bv.x; o0.y = acc[fi][fj][1] + bv.y;
            o1.x = acc[fi][fj][2] + bv.x; o1.y = acc[fi][fj][3] + bv.y;
            if (EPI == 0){
                o0.x = silu_f(o0.x); o0.y = silu_f(o0.y);
                o1.x = silu_f(o1.x); o1.y = silu_f(o1.y);
            } else {
                float2 r0 = *(const float2*)(resid + (size_t)m0*N + n);
                float2 r1 = *(const float2*)(resid + (size_t)(m0+8)*N + n);
                o0.x += r0.x; o0.y += r0.y;
                o1.x += r1.x; o1.y += r1.y;
            }
            *(float2*)(C + (size_t)m0*N + n)     = o0;
            *(float2*)(C + (size_t)(m0+8)*N + n) = o1;
        }
    }
}

// ---------------- 3. RoPE + gates + head transpose (tf32 pre-round) ----------------
__global__ void rope_gate_kernel(const float* __restrict__ qg,
                                 const float* __restrict__ kg,
                                 const float* __restrict__ vg)
{
    int tid = blockIdx.x * blockDim.x + threadIdx.x;
    int d  = tid & 31;
    int hh = (tid >> 5) & 15;
    int l  = (tid >> 9) & 2047;
    int b  = tid >> 20;
    if (b >= NB) return;
    size_t row   = (size_t)b*NL + l;
    size_t hbase = row * HID;
    float p   = g_pos[row];
    float inv = expf(-(float)d * (9.210340371976184f / 32.0f));
    float fr  = p * inv;
    float sn, cs;
    sincosf(fr, &sn, &cs);
    size_t ob = (((size_t)b*NH + hh)*NL + l)*NDH;
    {
        float2 e = *(const float2*)(&g_h[hbase + 2*ND + hh*NDH + 2*d]);
        float gq = qg[row*NH + hh];
        g_q[ob + d]      = tf32_rnd((e.x*cs - e.y*sn) * gq);
        g_q[ob + d + 32] = tf32_rnd((e.x*sn + e.y*cs) * gq);
    }
    {
        float2 e = *(const float2*)(&g_h[hbase + 3*ND + hh*NDH + 2*d]);
        float gk = kg[row*NH + hh];
        g_k[ob + d]      = tf32_rnd((e.x*cs - e.y*sn) * gk);
        g_k[ob + d + 32] = tf32_rnd((e.x*sn + e.y*cs) * gk);
    }
    {
        float gv = vg[row*NH + hh];
        g_v[ob + d]      = tf32_rnd(g_h[hbase + ND + hh*NDH + d]      * gv);
        g_v[ob + d + 32] = tf32_rnd(g_h[hbase + ND + hh*NDH + d + 32] * gv);
    }
}

// ---------------- 4. tf32 mma attention (R11 structure + fast silu) ----------------
// CTA: 64 q-rows for one (b,h); 8 warps. 4-slot KV ring, 3-ahead prefetch.
// QK^T: warp w -> m-rows (w>>1)*16, key-half (w&1)*16. Q frags in regs.
// S@V : same m-rows, d-half (w&1)*32. S round-trip synced per warp PAIR (bar.sync).
#define AST 68
#define SST 36
#define ABK 32
#define A_KV_F (2*ABK*AST)                 // floats per KV slot
#define A_QS_F (64*AST)                    // Q region (>= 64*SST S region)
#define A_SMEM_BYTES ((A_QS_F + 4*A_KV_F)*4)   // 87040

__global__ void __launch_bounds__(256, 2)
attn_mma(const float* __restrict__ bias, const float* __restrict__ head_scale)
{
    extern __shared__ float sm[];
    float* Qs = sm;                    // [64][AST], later reused as Ss [64][SST]
    float* Ss = sm;
    float* KV = sm + A_QS_F;           // [4][{K,V}][ABK][AST]

    const int ib = (int)gridDim.x - 1 - (int)blockIdx.x;   // big tiles first
    const int bh = blockIdx.y;
    const int b  = bh >> 4, hh = bh & 15;
    const int tid = threadIdx.x, lane = tid & 31, wid = tid >> 5;
    const int g = lane >> 2, t = lane & 3;
    const int r0 = (wid >> 1) * 16;        // warp m-rows
    const int kh = (wid & 1);              // key-half / d-half selector
    const int pair_bar = 1 + (wid >> 1);   // named barrier per warp pair

    const int njb = 2*(ib + 1);

    auto load_kv = [&](int slot, int jb){
        if (jb < njb){
            float* Ks = KV + slot*A_KV_F;
            float* Vs = Ks + ABK*AST;
            const float* kp = g_k + ((size_t)bh*NL + (size_t)jb*ABK)*NDH;
            const float* vp = g_v + ((size_t)bh*NL + (size_t)jb*ABK)*NDH;
            #pragma unroll
            for (int it = 0; it < 4; it++){
                int idx = tid + it*256;      // 0..1023
                int isV = idx >> 9;
                int li  = idx & 511;
                int row = li >> 4;
                int c16 = li & 15;
                float* dst = (isV ? Vs : Ks) + row*AST + c16*4;
                const float* src = (isV ? vp : kp) + row*64 + c16*4;
                cp_async16(smem_u32(dst), src);
            }
        }
        CP_COMMIT();
    };

    {   // group 0: Q tile (64 rows x 16 chunks)
        const float* qp = g_q + ((size_t)bh*NL + (size_t)ib*64)*NDH;
        #pragma unroll
        for (int it = 0; it < 4; it++){
            int idx = tid + it*256;
            int row = idx >> 4;
            int c16 = idx & 15;
            cp_async16(smem_u32(Qs + row*AST + c16*4), qp + row*64 + c16*4);
        }
        CP_COMMIT();
    }
    load_kv(0, 0);      // group 1
    load_kv(1, 1);      // group 2
    load_kv(2, 2);      // group 3

    // wait for Q (group0) + slot0 (group1); hoist Q fragments to registers
    CP_WAIT(2);
    __syncthreads();
    uint32_t Qa[8][4];
    {
        const float* qw = Qs + (r0 + g)*AST + t;
        #pragma unroll
        for (int ks = 0; ks < 8; ks++){
            Qa[ks][0] = __float_as_uint(qw[ks*8]);
            Qa[ks][1] = __float_as_uint(qw[8*AST + ks*8]);
            Qa[ks][2] = __float_as_uint(qw[ks*8 + 4]);
            Qa[ks][3] = __float_as_uint(qw[8*AST + ks*8 + 4]);
        }
    }
    __syncthreads();    // all warps done reading Q before S region reuse

    const float scale = head_scale[hh];
    float Yc[4][4];
    #pragma unroll
    for (int j = 0; j < 4; j++)
        #pragma unroll
        for (int c = 0; c < 4; c++) Yc[j][c] = 0.0f;

    const int ig0 = ib*64 + r0 + g;

    for (int jb = 0; jb < njb; ++jb){
        int slot = jb & 3;
        CP_WAIT(2);
        __syncthreads();                       // slot ready; prev iter fully done
        load_kv((jb + 3) & 3, jb + 3);         // refill (empty commit if beyond)

        // bias prefetch (latency hidden under QK mma loop)
        float2 pb0[2], pb1[2];
        {
            const float* bp = bias + ((size_t)b*NL + ig0)*NL + jb*ABK + kh*16 + 2*t;
            #pragma unroll
            for (int nf = 0; nf < 2; nf++){
                pb0[nf] = *(const float2*)(bp + nf*8);
                pb1[nf] = *(const float2*)(bp + nf*8 + (size_t)8*NL);
            }
        }

        const float* Ksb = KV + slot*A_KV_F;
        const float* Vsb = Ksb + ABK*AST;

        // ---- S = Q @ K^T  (keys kh*16 .. kh*16+15) ----
        float Sc[2][4];
        #pragma unroll
        for (int nf = 0; nf < 2; nf++)
            #pragma unroll
            for (int c = 0; c < 4; c++) Sc[nf][c] = 0.0f;

        const float* Bw = Ksb + (kh*16 + g)*AST + t;
        #pragma unroll
        for (int ks = 0; ks < 8; ks++){
            #pragma unroll
            for (int nf = 0; nf < 2; nf++){
                uint32_t bf[2];
                bf[0] = __float_as_uint(Bw[nf*8*AST + ks*8]);
                bf[1] = __float_as_uint(Bw[nf*8*AST + ks*8 + 4]);
                MMA16N8K8(Sc[nf], Qa[ks], bf);
            }
        }

        // ---- epilogue: scale + 4*bias + fast silu + causal -> Ss ----
        #pragma unroll
        for (int nf = 0; nf < 2; nf++){
            int lc = kh*16 + nf*8 + 2*t;
            int jg = jb*ABK + lc;
            float z00 = silu_f(fmaf(Sc[nf][0], scale, 4.0f*pb0[nf].x));
            float z01 = silu_f(fmaf(Sc[nf][1], scale, 4.0f*pb0[nf].y));
            float z10 = silu_f(fmaf(Sc[nf][2], scale, 4.0f*pb1[nf].x));
            float z11 = silu_f(fmaf(Sc[nf][3], scale, 4.0f*pb1[nf].y));
            if (jg     > ig0    ) z00 = 0.0f;
            if (jg + 1 > ig0    ) z01 = 0.0f;
            if (jg     > ig0 + 8) z10 = 0.0f;
            if (jg + 1 > ig0 + 8) z11 = 0.0f;
            float2 s0, s1;
            s0.x = tf32_rnd(z00); s0.y = tf32_rnd(z01);
            s1.x = tf32_rnd(z10); s1.y = tf32_rnd(z11);
            *(float2*)&Ss[(r0+g)*SST + lc]   = s0;
            *(float2*)&Ss[(r0+8+g)*SST + lc] = s1;
        }
        // pair-scoped barrier: only the 2 warps sharing rows r0..r0+15 exchange S
        asm volatile("bar.sync %0, %1;" :: "r"(pair_bar), "r"(64) : "memory");

        // ---- Y += S @ V  (d-cols kh*32 .. kh*32+31) ----
        const float* Aw2 = Ss + (r0 + g)*SST + t;
        #pragma unroll
        for (int ks = 0; ks < 4; ks++){
            uint32_t a[4];
            a[0] = __float_as_uint(Aw2[ks*8]);
            a[1] = __float_as_uint(Aw2[8*SST + ks*8]);
            a[2] = __float_as_uint(Aw2[ks*8 + 4]);
            a[3] = __float_as_uint(Aw2[8*SST + ks*8 + 4]);
            #pragma unroll
            for (int nf = 0; nf < 4; nf++){
                int dc = kh*32 + nf*8 + g;
                uint32_t bf[2];
                bf[0] = __float_as_uint(Vsb[(ks*8 + t)*AST + dc]);
                bf[1] = __float_as_uint(Vsb[(ks*8 + t + 4)*AST + dc]);
                MMA16N8K8(Yc[nf], a, bf);
            }
        }
    }

    // ---- final: ym = Y * u, tf32-rounded (GEMM2 A operand) ----
    {
        int l = ib*64 + r0 + g;
        size_t row0 = (size_t)b*NL + l;
        #pragma unroll
        for (int nf = 0; nf < 4; nf++){
            int d0 = kh*32 + nf*8 + 2*t;
            float2 u0 = *(const float2*)&g_h[row0*HID + hh*NDH + d0];
            float2 u1 = *(const float2*)&g_h[(row0+8)*HID + hh*NDH + d0];
            float2 o0, o1;
            o0.x = tf32_rnd(Yc[nf][0]*u0.x); o0.y = tf32_rnd(Yc[nf][1]*u0.y);
            o1.x = tf32_rnd(Yc[nf][2]*u1.x); o1.y = tf32_rnd(Yc[nf][3]*u1.y);
            *(float2*)&g_ym[row0*ND + hh*NDH + d0]     = o0;
            *(float2*)&g_ym[(row0+8)*ND + hh*NDH + d0] = o1;
        }
    }
}

// ---------------- 6. LayerNorm ----------------
__global__ void ln_kernel(const float* __restrict__ z, const float* __restrict__ gamma,
                          const float* __restrict__ beta, float* __restrict__ out)
{
    __shared__ float rs[8], rq[8], mv[2];
    int row = blockIdx.x;
    int t = threadIdx.x;
    const float4* zr = (const float4*)(z + (size_t)row * ND);
    float4 v = zr[t];
    float s  = v.x + v.y + v.z + v.w;
    float sq = v.x*v.x + v.y*v.y + v.z*v.z + v.w*v.w;
    #pragma unroll
    for (int o = 16; o; o >>= 1){
        s  += __shfl_down_sync(0xffffffffu, s,  o);
        sq += __shfl_down_sync(0xffffffffu, sq, o);
    }
    if ((t & 31) == 0){ rs[t>>5] = s; rq[t>>5] = sq; }
    __syncthreads();
    if (t == 0){
        float S = 0.f, Q = 0.f;
        #pragma unroll
        for (int i = 0; i < 8; i++){ S += rs[i]; Q += rq[i]; }
        float mean = S * (1.0f/ND);
        float var  = Q * (1.0f/ND) - mean*mean;
        mv[0] = mean; mv[1] = rsqrtf(var + 1e-5f);
    }
    __syncthreads();
    float mean = mv[0], rstd = mv[1];
    float4 g  = ((const float4*)gamma)[t];
    float4 be = ((const float4*)beta )[t];
    float4 o;
    o.x = (v.x - mean)*rstd*g.x + be.x;
    o.y = (v.y - mean)*rstd*g.y + be.y;
    o.z = (v.z - mean)*rstd*g.z + be.z;
    o.w = (v.w - mean)*rstd*g.w + be.w;
    ((float4*)(out + (size_t)row * ND))[t] = o;
}

// ---------------- launch ----------------
extern "C" void kernel_launch(void* const* d_in, const int* in_sizes, int n_in,
                              void* d_out, int out_size)
{
    const float* x   = (const float*)d_in[0];
    const float* rl  = (const float*)d_in[3];
    const float* qg  = (const float*)d_in[4];
    const float* kg  = (const float*)d_in[5];
    const float* vg  = (const float*)d_in[6];
    const float* tpb = (const float*)d_in[7];
    const float* pw  = (const float*)d_in[8];
    const float* pb  = (const float*)d_in[9];
    const float* ow  = (const float*)d_in[10];
    const float* ob  = (const float*)d_in[11];
    const float* hs  = (const float*)d_in[12];
    const float* lg  = (const float*)d_in[13];
    const float* lb  = (const float*)d_in[14];
    float* out = (float*)d_out;

    float *hp, *ymp, *zp, *xrp, *pwrp, *owrp;
    cudaGetSymbolAddress((void**)&hp,   g_h);
    cudaGetSymbolAddress((void**)&ymp,  g_ym);
    cudaGetSymbolAddress((void**)&zp,   g_z);
    cudaGetSymbolAddress((void**)&xrp,  g_xr);
    cudaGetSymbolAddress((void**)&pwrp, g_pwr);
    cudaGetSymbolAddress((void**)&owrp, g_owr);

    cudaFuncSetAttribute(gemm_mma<0>, cudaFuncAttributeMaxDynamicSharedMemorySize, G_SMEM_BYTES);
    cudaFuncSetAttribute(gemm_mma<1>, cudaFuncAttributeMaxDynamicSharedMemorySize, G_SMEM_BYTES);
    cudaFuncSetAttribute(attn_mma,    cudaFuncAttributeMaxDynamicSharedMemorySize, A_SMEM_BYTES);

    // 0. tf32 pre-rounding of GEMM operands (removes cvt from GEMM hot loops)
    round_tf32_kernel<<<(MROWS*ND/4 + 255)/256, 256>>>(x,  xrp,  MROWS*ND/4);
    round_tf32_kernel<<<(HID*ND/4   + 255)/256, 256>>>(pw, pwrp, HID*ND/4);
    round_tf32_kernel<<<(ND*ND/4    + 255)/256, 256>>>(ow, owrp, ND*ND/4);

    // 1. positions
    cumsum_kernel<<<NB, 1024>>>(rl);

    // 2. h = silu(x @ proj_w^T + proj_b)   [tf32 mma, pre-rounded operands]
    gemm_mma<0><<<dim3(HID/128, MROWS/128), 256, G_SMEM_BYTES>>>(xrp, pwrp, pb, nullptr, hp, HID, ND);

    // 3. rope + gates + head transpose (+ tf32 pre-round of q/k/v)
    rope_gate_kernel<<<(NB*NL*NH*32)/256, 256>>>(qg, kg, vg);

    // 4. fused attention + u-gate   [tf32 mma]
    attn_mma<<<dim3(NL/64, NB*NH), 256, A_SMEM_BYTES>>>(tpb, hs);

    // 5. z = ym @ out_w^T + out_b + x   [tf32 mma; ym pre-rounded in attn epilogue]
    gemm_mma<1><<<dim3(ND/128, MROWS/128), 256, G_SMEM_BYTES>>>(ymp, owrp, ob, x, zp, ND, ND);

    // 6. layernorm
    ln_kernel<<<MROWS, 256>>>(zp, lg, lb, out);
}

// round 14
// speedup vs baseline: 1.4610x; 1.4610x over previous
#include <cuda_runtime.h>
#include <math.h>
#include <stdint.h>

#define NB 2
#define NL 2048
#define ND 1024
#define NH 16
#define NDH 64
#define MROWS (NB*NL)   // 4096
#define HID (4*ND)      // 4096

// ---------------- scratch ----------------
__device__ float g_h  [(size_t)MROWS * HID];
__device__ float g_q  [(size_t)NB*NH*NL*NDH];
__device__ float g_k  [(size_t)NB*NH*NL*NDH];
__device__ float g_v  [(size_t)NB*NH*NL*NDH];
__device__ float g_ym [(size_t)MROWS * ND];
__device__ float g_z  [(size_t)MROWS * ND];
__device__ float g_pos[NB*NL];

// fast silu: x * rcp(1+exp(-x)); ~5 instrs vs ~20 precise; rel err ~1e-6
__device__ __forceinline__ float silu_f(float x){
    return __fdividef(x, 1.0f + __expf(-x));
}

__device__ __forceinline__ uint32_t tf32_bits(float x){
    uint32_t u; asm("cvt.rna.tf32.f32 %0, %1;" : "=r"(u) : "f"(x));
    return u;
}
__device__ __forceinline__ float tf32_rnd(float x){ return __uint_as_float(tf32_bits(x)); }

__device__ __forceinline__ uint32_t smem_u32(const void* p){
    uint32_t a;
    asm("{ .reg .u64 t; cvta.to.shared.u64 t, %1; cvt.u32.u64 %0, t; }" : "=r"(a) : "l"(p));
    return a;
}
__device__ __forceinline__ void cp_async16(uint32_t saddr, const void* g){
    asm volatile("cp.async.cg.shared.global [%0], [%1], 16;" :: "r"(saddr), "l"(g));
}
#define CP_COMMIT()  asm volatile("cp.async.commit_group;" ::: "memory")
#define CP_WAIT(n)   asm volatile("cp.async.wait_group %0;" :: "n"(n) : "memory")

#define MMA16N8K8(c, a, b) \
    asm volatile("mma.sync.aligned.m16n8k8.row.col.f32.tf32.tf32.f32 " \
        "{%0,%1,%2,%3}, {%4,%5,%6,%7}, {%8,%9}, {%0,%1,%2,%3};" \
        : "+f"((c)[0]), "+f"((c)[1]), "+f"((c)[2]), "+f"((c)[3]) \
        : "r"((a)[0]), "r"((a)[1]), "r"((a)[2]), "r"((a)[3]), \
          "r"((b)[0]), "r"((b)[1]))

// ---------------- 1. cumsum of rope_lambda -> g_pos ----------------
__global__ void cumsum_kernel(const float* __restrict__ rl)
{
    __shared__ float s[1024];
    int b = blockIdx.x, t = threadIdx.x;
    const float* a = rl + (size_t)b * NL;
    float x0 = a[2*t], x1 = a[2*t+1];
    float sum = x0 + x1;
    s[t] = sum;
    __syncthreads();
    for (int off = 1; off < 1024; off <<= 1){
        float v = (t >= off) ? s[t-off] : 0.0f;
        __syncthreads();
        s[t] += v;
        __syncthreads();
    }
    float incl = s[t];
    g_pos[b*NL + 2*t]     = incl - x1;
    g_pos[b*NL + 2*t + 1] = incl;
}

// ---------------- 2/5. tf32 mma.sync GEMM (NT), 3-stage ----------------
#define GSTAGES 3
#define GKC 32
#define G_STRIDE 36
#define G_TILE_F (128*G_STRIDE)
#define G_TILE_B (G_TILE_F*4)
#define G_SMEM_BYTES (GSTAGES * 2 * G_TILE_B)   // 110592

template<int EPI>
__global__ void __launch_bounds__(256, 2)
gemm_mma(const float* __restrict__ A, const float* __restrict__ Bw,
         const float* __restrict__ bias, const float* __restrict__ resid,
         float* __restrict__ C, int N, int K)
{
    extern __shared__ float dsm[];
    const uint32_t sb = smem_u32(dsm);
    const int tid  = threadIdx.x;
    const int lane = tid & 31, wid = tid >> 5;
    const int wm = wid >> 2, wn = wid & 3;
    const int g  = lane >> 2, t = lane & 3;
    const int bn = blockIdx.x * 128;
    const int bm = blockIdx.y * 128;

    float acc[4][4][4];
    #pragma unroll
    for (int i = 0; i < 4; i++)
        #pragma unroll
        for (int j = 0; j < 4; j++)
            #pragma unroll
            for (int c = 0; c < 4; c++) acc[i][j][c] = 0.0f;

    auto load_stage = [&](int s, int kt){
        uint32_t base = sb + (uint32_t)s * (2*G_TILE_B);
        #pragma unroll
        for (int it = 0; it < 8; it++){
            int idx = tid + it*256;
            int isB = idx >> 10;
            int li  = idx & 1023;
            int row = li >> 3;
            int c16 = li & 7;
            const float* src = (isB ? (Bw + (size_t)(bn+row)*K)
                                    : (A  + (size_t)(bm+row)*K)) + kt + c16*4;
            cp_async16(base + (uint32_t)isB*G_TILE_B + (uint32_t)(row*144 + c16*16), src);
        }
        CP_COMMIT();
    };

    #pragma unroll
    for (int s = 0; s < GSTAGES; s++) load_stage(s, s*GKC);

    const int NCH = K / GKC;
    int s = 0;
    for (int ch = 0; ch < NCH; ch++){
        CP_WAIT(GSTAGES-1);
        __syncthreads();

        const float* As = dsm + (size_t)s*2*G_TILE_F;
        const float* Bs = As + G_TILE_F;
        const float* Awp = As + (wm*64 + g)*G_STRIDE + t;
        const float* Bwp = Bs + (wn*32 + g)*G_STRIDE + t;

        #pragma unroll
        for (int ks = 0; ks < 4; ks++){
            int k0 = ks*8;
            uint32_t b[4][2];
            #pragma unroll
            for (int fj = 0; fj < 4; fj++){
                const float* bp = Bwp + fj*8*G_STRIDE + k0;
                b[fj][0] = tf32_bits(bp[0]);
                b[fj][1] = tf32_bits(bp[4]);
            }
            #pragma unroll
            for (int fi = 0; fi < 4; fi++){
                const float* ap = Awp + fi*16*G_STRIDE + k0;
                uint32_t a[4];
                a[0] = tf32_bits(ap[0]);
                a[1] = tf32_bits(ap[8*G_STRIDE]);
                a[2] = tf32_bits(ap[4]);
                a[3] = tf32_bits(ap[8*G_STRIDE+4]);
                #pragma unroll
                for (int fj = 0; fj < 4; fj++)
                    MMA16N8K8(acc[fi][fj], a, b[fj]);
            }
        }
        __syncthreads();
        if (ch + GSTAGES < NCH) load_stage(s, (ch + GSTAGES)*GKC);
        if (++s == GSTAGES) s = 0;
    }

    #pragma unroll
    for (int fi = 0; fi < 4; fi++){
        int m0 = bm + wm*64 + fi*16 + g;
        #pragma unroll
        for (int fj = 0; fj < 4; fj++){
            int n = bn + wn*32 + fj*8 + 2*t;
            float2 bv = *(const float2*)(bias + n);
            float2 o0, o1;
            o0.x = acc[fi][fj][0] + bv.x; o0.y = acc[fi][fj][1] + bv.y;
            o1.x = acc[fi][fj][2] + bv.x; o1.y = acc[fi][fj][3] + bv.y;
            if (EPI == 0){
                o0.x = silu_f(o0.x); o0.y = silu_f(o0.y);
                o1.x = silu_f(o1.x); o1.y = silu_f(o1.y);
            } else {
                float2 r0 = *(const float2*)(resid + (size_t)m0*N + n);
                float2 r1 = *(const float2*)(resid + (size_t)(m0+8)*N + n);
                o0.x += r0.x; o0.y += r0.y;
                o1.x += r1.x; o1.y += r1.y;
            }
            *(float2*)(C + (size_t)m0*N + n)     = o0;
            *(float2*)(C + (size_t)(m0+8)*N + n) = o1;
        }
    }
}

// ---------------- 3. RoPE + gates + head transpose (tf32 pre-round) ----------------
__global__ void rope_gate_kernel(const float* __restrict__ qg,
                                 const float* __restrict__ kg,
                                 const float* __restrict__ vg)
{
    int tid = blockIdx.x * blockDim.x + threadIdx.x;
    int d  = tid & 31;
    int hh = (tid >> 5) & 15;
    int l  = (tid >> 9) & 2047;
    int b  = tid >> 20;
    if (b >= NB) return;
    size_t row   = (size_t)b*NL + l;
    size_t hbase = row * HID;
    float p   = g_pos[row];
    float inv = expf(-(float)d * (9.210340371976184f / 32.0f));
    float fr  = p * inv;
    float sn, cs;
    sincosf(fr, &sn, &cs);
    size_t ob = (((size_t)b*NH + hh)*NL + l)*NDH;
    {
        float2 e = *(const float2*)(&g_h[hbase + 2*ND + hh*NDH + 2*d]);
        float gq = qg[row*NH + hh];
        g_q[ob + d]      = tf32_rnd((e.x*cs - e.y*sn) * gq);
        g_q[ob + d + 32] = tf32_rnd((e.x*sn + e.y*cs) * gq);
    }
    {
        float2 e = *(const float2*)(&g_h[hbase + 3*ND + hh*NDH + 2*d]);
        float gk = kg[row*NH + hh];
        g_k[ob + d]      = tf32_rnd((e.x*cs - e.y*sn) * gk);
        g_k[ob + d + 32] = tf32_rnd((e.x*sn + e.y*cs) * gk);
    }
    {
        float gv = vg[row*NH + hh];
        g_v[ob + d]      = tf32_rnd(g_h[hbase + ND + hh*NDH + d]      * gv);
        g_v[ob + d + 32] = tf32_rnd(g_h[hbase + ND + hh*NDH + d + 32] * gv);
    }
}

// ---------------- 4. tf32 mma attention (R11 structure, fast silu) ----------------
// CTA: 64 q-rows for one (b,h); 8 warps. 4-slot KV ring, 3-ahead prefetch.
// QK^T: warp w -> m-rows (w>>1)*16, key-half (w&1)*16. Q frags in regs.
// S@V : same m-rows, d-half (w&1)*32. S round-trip synced per warp PAIR (bar.sync).
#define AST 68
#define SST 36
#define ABK 32
#define A_KV_F (2*ABK*AST)                 // floats per KV slot
#define A_QS_F (64*AST)                    // Q region (>= 64*SST S region)
#define A_SMEM_BYTES ((A_QS_F + 4*A_KV_F)*4)   // 87040

__global__ void __launch_bounds__(256, 2)
attn_mma(const float* __restrict__ bias, const float* __restrict__ head_scale)
{
    extern __shared__ float sm[];
    float* Qs = sm;                    // [64][AST], later reused as Ss [64][SST]
    float* Ss = sm;
    float* KV = sm + A_QS_F;           // [4][{K,V}][ABK][AST]

    const int ib = (int)gridDim.x - 1 - (int)blockIdx.x;   // big tiles first
    const int bh = blockIdx.y;
    const int b  = bh >> 4, hh = bh & 15;
    const int tid = threadIdx.x, lane = tid & 31, wid = tid >> 5;
    const int g = lane >> 2, t = lane & 3;
    const int r0 = (wid >> 1) * 16;        // warp m-rows
    const int kh = (wid & 1);              // key-half / d-half selector
    const int pair_bar = 1 + (wid >> 1);   // named barrier per warp pair

    const int njb = 2*(ib + 1);

    auto load_kv = [&](int slot, int jb){
        if (jb < njb){
            float* Ks = KV + slot*A_KV_F;
            float* Vs = Ks + ABK*AST;
            const float* kp = g_k + ((size_t)bh*NL + (size_t)jb*ABK)*NDH;
            const float* vp = g_v + ((size_t)bh*NL + (size_t)jb*ABK)*NDH;
            #pragma unroll
            for (int it = 0; it < 4; it++){
                int idx = tid + it*256;      // 0..1023
                int isV = idx >> 9;
                int li  = idx & 511;
                int row = li >> 4;
                int c16 = li & 15;
                float* dst = (isV ? Vs : Ks) + row*AST + c16*4;
                const float* src = (isV ? vp : kp) + row*64 + c16*4;
                cp_async16(smem_u32(dst), src);
            }
        }
        CP_COMMIT();
    };

    {   // group 0: Q tile (64 rows x 16 chunks)
        const float* qp = g_q + ((size_t)bh*NL + (size_t)ib*64)*NDH;
        #pragma unroll
        for (int it = 0; it < 4; it++){
            int idx = tid + it*256;
            int row = idx >> 4;
            int c16 = idx & 15;
            cp_async16(smem_u32(Qs + row*AST + c16*4), qp + row*64 + c16*4);
        }
        CP_COMMIT();
    }
    load_kv(0, 0);      // group 1
    load_kv(1, 1);      // group 2
    load_kv(2, 2);      // group 3

    // wait for Q (group0) + slot0 (group1); hoist Q fragments to registers
    CP_WAIT(2);
    __syncthreads();
    uint32_t Qa[8][4];
    {
        const float* qw = Qs + (r0 + g)*AST + t;
        #pragma unroll
        for (int ks = 0; ks < 8; ks++){
            Qa[ks][0] = __float_as_uint(qw[ks*8]);
            Qa[ks][1] = __float_as_uint(qw[8*AST + ks*8]);
            Qa[ks][2] = __float_as_uint(qw[ks*8 + 4]);
            Qa[ks][3] = __float_as_uint(qw[8*AST + ks*8 + 4]);
        }
    }
    __syncthreads();    // all warps done reading Q before S region reuse

    const float scale = head_scale[hh];
    float Yc[4][4];
    #pragma unroll
    for (int j = 0; j < 4; j++)
        #pragma unroll
        for (int c = 0; c < 4; c++) Yc[j][c] = 0.0f;

    const int ig0 = ib*64 + r0 + g;

    for (int jb = 0; jb < njb; ++jb){
        int slot = jb & 3;
        CP_WAIT(2);
        __syncthreads();                       // slot ready; prev iter fully done
        load_kv((jb + 3) & 3, jb + 3);         // refill (empty commit if beyond)

        // bias prefetch (latency hidden under QK mma loop)
        float2 pb0[2], pb1[2];
        {
            const float* bp = bias + ((size_t)b*NL + ig0)*NL + jb*ABK + kh*16 + 2*t;
            #pragma unroll
            for (int nf = 0; nf < 2; nf++){
                pb0[nf] = *(const float2*)(bp + nf*8);
                pb1[nf] = *(const float2*)(bp + nf*8 + (size_t)8*NL);
            }
        }

        const float* Ksb = KV + slot*A_KV_F;
        const float* Vsb = Ksb + ABK*AST;

        // ---- S = Q @ K^T  (keys kh*16 .. kh*16+15) ----
        float Sc[2][4];
        #pragma unroll
        for (int nf = 0; nf < 2; nf++)
            #pragma unroll
            for (int c = 0; c < 4; c++) Sc[nf][c] = 0.0f;

        const float* Bw = Ksb + (kh*16 + g)*AST + t;
        #pragma unroll
        for (int ks = 0; ks < 8; ks++){
            #pragma unroll
            for (int nf = 0; nf < 2; nf++){
                uint32_t bf[2];
                bf[0] = __float_as_uint(Bw[nf*8*AST + ks*8]);
                bf[1] = __float_as_uint(Bw[nf*8*AST + ks*8 + 4]);
                MMA16N8K8(Sc[nf], Qa[ks], bf);
            }
        }

        // ---- epilogue: scale + 4*bias + fast silu + causal -> Ss ----
        #pragma unroll
        for (int nf = 0; nf < 2; nf++){
            int lc = kh*16 + nf*8 + 2*t;
            int jg = jb*ABK + lc;
            float z00 = silu_f(fmaf(Sc[nf][0], scale, 4.0f*pb0[nf].x));
            float z01 = silu_f(fmaf(Sc[nf][1], scale, 4.0f*pb0[nf].y));
            float z10 = silu_f(fmaf(Sc[nf][2], scale, 4.0f*pb1[nf].x));
            float z11 = silu_f(fmaf(Sc[nf][3], scale, 4.0f*pb1[nf].y));
            if (jg     > ig0    ) z00 = 0.0f;
            if (jg + 1 > ig0    ) z01 = 0.0f;
            if (jg     > ig0 + 8) z10 = 0.0f;
            if (jg + 1 > ig0 + 8) z11 = 0.0f;
            float2 s0, s1;
            s0.x = tf32_rnd(z00); s0.y = tf32_rnd(z01);
            s1.x = tf32_rnd(z10); s1.y = tf32_rnd(z11);
            *(float2*)&Ss[(r0+g)*SST + lc]   = s0;
            *(float2*)&Ss[(r0+8+g)*SST + lc] = s1;
        }
        // pair-scoped barrier: only the 2 warps sharing rows r0..r0+15 exchange S
        asm volatile("bar.sync %0, %1;" :: "r"(pair_bar), "r"(64) : "memory");

        // ---- Y += S @ V  (d-cols kh*32 .. kh*32+31) ----
        const float* Aw2 = Ss + (r0 + g)*SST + t;
        #pragma unroll
        for (int ks = 0; ks < 4; ks++){
            uint32_t a[4];
            a[0] = __float_as_uint(Aw2[ks*8]);
            a[1] = __float_as_uint(Aw2[8*SST + ks*8]);
            a[2] = __float_as_uint(Aw2[ks*8 + 4]);
            a[3] = __float_as_uint(Aw2[8*SST + ks*8 + 4]);
            #pragma unroll
            for (int nf = 0; nf < 4; nf++){
                int dc = kh*32 + nf*8 + g;
                uint32_t bf[2];
                bf[0] = __float_as_uint(Vsb[(ks*8 + t)*AST + dc]);
                bf[1] = __float_as_uint(Vsb[(ks*8 + t + 4)*AST + dc]);
                MMA16N8K8(Yc[nf], a, bf);
            }
        }
    }

    // ---- final: ym = Y * u ----
    {
        int l = ib*64 + r0 + g;
        size_t row0 = (size_t)b*NL + l;
        #pragma unroll
        for (int nf = 0; nf < 4; nf++){
            int d0 = kh*32 + nf*8 + 2*t;
            float2 u0 = *(const float2*)&g_h[row0*HID + hh*NDH + d0];
            float2 u1 = *(const float2*)&g_h[(row0+8)*HID + hh*NDH + d0];
            float2 o0, o1;
            o0.x = Yc[nf][0]*u0.x; o0.y = Yc[nf][1]*u0.y;
            o1.x = Yc[nf][2]*u1.x; o1.y = Yc[nf][3]*u1.y;
            *(float2*)&g_ym[row0*ND + hh*NDH + d0]     = o0;
            *(float2*)&g_ym[(row0+8)*ND + hh*NDH + d0] = o1;
        }
    }
}

// ---------------- 6. LayerNorm ----------------
__global__ void ln_kernel(const float* __restrict__ z, const float* __restrict__ gamma,
                          const float* __restrict__ beta, float* __restrict__ out)
{
    __shared__ float rs[8], rq[8], mv[2];
    int row = blockIdx.x;
    int t = threadIdx.x;
    const float4* zr = (const float4*)(z + (size_t)row * ND);
    float4 v = zr[t];
    float s  = v.x + v.y + v.z + v.w;
    float sq = v.x*v.x + v.y*v.y + v.z*v.z + v.w*v.w;
    #pragma unroll
    for (int o = 16; o; o >>= 1){
        s  += __shfl_down_sync(0xffffffffu, s,  o);
        sq += __shfl_down_sync(0xffffffffu, sq, o);
    }
    if ((t & 31) == 0){ rs[t>>5] = s; rq[t>>5] = sq; }
    __syncthreads();
    if (t == 0){
        float S = 0.f, Q = 0.f;
        #pragma unroll
        for (int i = 0; i < 8; i++){ S += rs[i]; Q += rq[i]; }
        float mean = S * (1.0f/ND);
        float var  = Q * (1.0f/ND) - mean*mean;
        mv[0] = mean; mv[1] = rsqrtf(var + 1e-5f);
    }
    __syncthreads();
    float mean = mv[0], rstd = mv[1];
    float4 g  = ((const float4*)gamma)[t];
    float4 be = ((const float4*)beta )[t];
    float4 o;
    o.x = (v.x - mean)*rstd*g.x + be.x;
    o.y = (v.y - mean)*rstd*g.y + be.y;
    o.z = (v.z - mean)*rstd*g.z + be.z;
    o.w = (v.w - mean)*rstd*g.w + be.w;
    ((float4*)(out + (size_t)row * ND))[t] = o;
}

// ---------------- launch ----------------
extern "C" void kernel_launch(void* const* d_in, const int* in_sizes, int n_in,
                              void* d_out, int out_size)
{
    const float* x   = (const float*)d_in[0];
    const float* rl  = (const float*)d_in[3];
    const float* qg  = (const float*)d_in[4];
    const float* kg  = (const float*)d_in[5];
    const float* vg  = (const float*)d_in[6];
    const float* tpb = (const float*)d_in[7];
    const float* pw  = (const float*)d_in[8];
    const float* pb  = (const float*)d_in[9];
    const float* ow  = (const float*)d_in[10];
    const float* ob  = (const float*)d_in[11];
    const float* hs  = (const float*)d_in[12];
    const float* lg  = (const float*)d_in[13];
    const float* lb  = (const float*)d_in[14];
    float* out = (float*)d_out;

    float *hp, *ymp, *zp;
    cudaGetSymbolAddress((void**)&hp,  g_h);
    cudaGetSymbolAddress((void**)&ymp, g_ym);
    cudaGetSymbolAddress((void**)&zp,  g_z);

    cudaFuncSetAttribute(gemm_mma<0>, cudaFuncAttributeMaxDynamicSharedMemorySize, G_SMEM_BYTES);
    cudaFuncSetAttribute(gemm_mma<1>, cudaFuncAttributeMaxDynamicSharedMemorySize, G_SMEM_BYTES);
    cudaFuncSetAttribute(attn_mma,    cudaFuncAttributeMaxDynamicSharedMemorySize, A_SMEM_BYTES);

    // 1. positions
    cumsum_kernel<<<NB, 1024>>>(rl);

    // 2. h = silu(x @ proj_w^T + proj_b)   [tf32 mma]
    gemm_mma<0><<<dim3(HID/128, MROWS/128), 256, G_SMEM_BYTES>>>(x, pw, pb, nullptr, hp, HID, ND);

    // 3. rope + gates + head transpose (+ tf32 pre-round of q/k/v)
    rope_gate_kernel<<<(NB*NL*NH*32)/256, 256>>>(qg, kg, vg);

    // 4. fused attention + u-gate   [tf32 mma]
    attn_mma<<<dim3(NL/64, NB*NH), 256, A_SMEM_BYTES>>>(tpb, hs);

    // 5. z = ym @ out_w^T + out_b + x   [tf32 mma]
    gemm_mma<1><<<dim3(ND/128, MROWS/128), 256, G_SMEM_BYTES>>>(ymp, ow, ob, x, zp, ND, ND);

    // 6. layernorm
    ln_kernel<<<MROWS, 256>>>(zp, lg, lb, out);
}

// round 15
// speedup vs baseline: 1.4641x; 1.0021x over previous
#include <cuda_runtime.h>
#include <math.h>
#include <stdint.h>

#define NB 2
#define NL 2048
#define ND 1024
#define NH 16
#define NDH 64
#define MROWS (NB*NL)   // 4096
#define HID (4*ND)      // 4096

// ---------------- scratch ----------------
__device__ float g_h  [(size_t)MROWS * HID];
__device__ float g_q  [(size_t)NB*NH*NL*NDH];
__device__ float g_k  [(size_t)NB*NH*NL*NDH];
__device__ float g_v  [(size_t)NB*NH*NL*NDH];
__device__ float g_ym [(size_t)MROWS * ND];
__device__ float g_z  [(size_t)MROWS * ND];
__device__ float g_pos[NB*NL];

// fast silu: x * rcp(1+exp(-x)); ~5 instrs vs ~20 precise; rel err ~1e-6
__device__ __forceinline__ float silu_f(float x){
    return __fdividef(x, 1.0f + __expf(-x));
}

__device__ __forceinline__ uint32_t tf32_bits(float x){
    uint32_t u; asm("cvt.rna.tf32.f32 %0, %1;" : "=r"(u) : "f"(x));
    return u;
}
__device__ __forceinline__ float tf32_rnd(float x){ return __uint_as_float(tf32_bits(x)); }

__device__ __forceinline__ uint32_t smem_u32(const void* p){
    uint32_t a;
    asm("{ .reg .u64 t; cvta.to.shared.u64 t, %1; cvt.u32.u64 %0, t; }" : "=r"(a) : "l"(p));
    return a;
}
__device__ __forceinline__ void cp_async16(uint32_t saddr, const void* g){
    asm volatile("cp.async.cg.shared.global [%0], [%1], 16;" :: "r"(saddr), "l"(g));
}
#define CP_COMMIT()  asm volatile("cp.async.commit_group;" ::: "memory")
#define CP_WAIT(n)   asm volatile("cp.async.wait_group %0;" :: "n"(n) : "memory")

#define MMA16N8K8(c, a, b) \
    asm volatile("mma.sync.aligned.m16n8k8.row.col.f32.tf32.tf32.f32 " \
        "{%0,%1,%2,%3}, {%4,%5,%6,%7}, {%8,%9}, {%0,%1,%2,%3};" \
        : "+f"((c)[0]), "+f"((c)[1]), "+f"((c)[2]), "+f"((c)[3]) \
        : "r"((a)[0]), "r"((a)[1]), "r"((a)[2]), "r"((a)[3]), \
          "r"((b)[0]), "r"((b)[1]))

// ---------------- 1. cumsum of rope_lambda -> g_pos ----------------
__global__ void cumsum_kernel(const float* __restrict__ rl)
{
    __shared__ float s[1024];
    int b = blockIdx.x, t = threadIdx.x;
    const float* a = rl + (size_t)b * NL;
    float x0 = a[2*t], x1 = a[2*t+1];
    float sum = x0 + x1;
    s[t] = sum;
    __syncthreads();
    for (int off = 1; off < 1024; off <<= 1){
        float v = (t >= off) ? s[t-off] : 0.0f;
        __syncthreads();
        s[t] += v;
        __syncthreads();
    }
    float incl = s[t];
    g_pos[b*NL + 2*t]     = incl - x1;
    g_pos[b*NL + 2*t + 1] = incl;
}

// ---------------- 2/5. tf32 mma.sync GEMM (NT), 3-stage ----------------
#define GSTAGES 3
#define GKC 32
#define G_STRIDE 36
#define G_TILE_F (128*G_STRIDE)
#define G_TILE_B (G_TILE_F*4)
#define G_SMEM_BYTES (GSTAGES * 2 * G_TILE_B)   // 110592

template<int EPI>
__global__ void __launch_bounds__(256, 2)
gemm_mma(const float* __restrict__ A, const float* __restrict__ Bw,
         const float* __restrict__ bias, const float* __restrict__ resid,
         float* __restrict__ C, int N, int K)
{
    extern __shared__ float dsm[];
    const uint32_t sb = smem_u32(dsm);
    const int tid  = threadIdx.x;
    const int lane = tid & 31, wid = tid >> 5;
    const int wm = wid >> 2, wn = wid & 3;
    const int g  = lane >> 2, t = lane & 3;
    const int bn = blockIdx.x * 128;
    const int bm = blockIdx.y * 128;

    float acc[4][4][4];
    #pragma unroll
    for (int i = 0; i < 4; i++)
        #pragma unroll
        for (int j = 0; j < 4; j++)
            #pragma unroll
            for (int c = 0; c < 4; c++) acc[i][j][c] = 0.0f;

    auto load_stage = [&](int s, int kt){
        uint32_t base = sb + (uint32_t)s * (2*G_TILE_B);
        #pragma unroll
        for (int it = 0; it < 8; it++){
            int idx = tid + it*256;
            int isB = idx >> 10;
            int li  = idx & 1023;
            int row = li >> 3;
            int c16 = li & 7;
            const float* src = (isB ? (Bw + (size_t)(bn+row)*K)
                                    : (A  + (size_t)(bm+row)*K)) + kt + c16*4;
            cp_async16(base + (uint32_t)isB*G_TILE_B + (uint32_t)(row*144 + c16*16), src);
        }
        CP_COMMIT();
    };

    #pragma unroll
    for (int s = 0; s < GSTAGES; s++) load_stage(s, s*GKC);

    const int NCH = K / GKC;
    int s = 0;
    for (int ch = 0; ch < NCH; ch++){
        CP_WAIT(GSTAGES-1);
        __syncthreads();

        const float* As = dsm + (size_t)s*2*G_TILE_F;
        const float* Bs = As + G_TILE_F;
        const float* Awp = As + (wm*64 + g)*G_STRIDE + t;
        const float* Bwp = Bs + (wn*32 + g)*G_STRIDE + t;

        #pragma unroll
        for (int ks = 0; ks < 4; ks++){
            int k0 = ks*8;
            uint32_t b[4][2];
            #pragma unroll
            for (int fj = 0; fj < 4; fj++){
                const float* bp = Bwp + fj*8*G_STRIDE + k0;
                b[fj][0] = tf32_bits(bp[0]);
                b[fj][1] = tf32_bits(bp[4]);
            }
            #pragma unroll
            for (int fi = 0; fi < 4; fi++){
                const float* ap = Awp + fi*16*G_STRIDE + k0;
                uint32_t a[4];
                a[0] = tf32_bits(ap[0]);
                a[1] = tf32_bits(ap[8*G_STRIDE]);
                a[2] = tf32_bits(ap[4]);
                a[3] = tf32_bits(ap[8*G_STRIDE+4]);
                #pragma unroll
                for (int fj = 0; fj < 4; fj++)
                    MMA16N8K8(acc[fi][fj], a, b[fj]);
            }
        }
        __syncthreads();
        if (ch + GSTAGES < NCH) load_stage(s, (ch + GSTAGES)*GKC);
        if (++s == GSTAGES) s = 0;
    }

    #pragma unroll
    for (int fi = 0; fi < 4; fi++){
        int m0 = bm + wm*64 + fi*16 + g;
        #pragma unroll
        for (int fj = 0; fj < 4; fj++){
            int n = bn + wn*32 + fj*8 + 2*t;
            float2 bv = *(const float2*)(bias + n);
            float2 o0, o1;
            o0.x = acc[fi][fj][0] + bv.x; o0.y = acc[fi][fj][1] + bv.y;
            o1.x = acc[fi][fj][2] + bv.x; o1.y = acc[fi][fj][3] + bv.y;
            if (EPI == 0){
                o0.x = silu_f(o0.x); o0.y = silu_f(o0.y);
                o1.x = silu_f(o1.x); o1.y = silu_f(o1.y);
            } else {
                float2 r0 = *(const float2*)(resid + (size_t)m0*N + n);
                float2 r1 = *(const float2*)(resid + (size_t)(m0+8)*N + n);
                o0.x += r0.x; o0.y += r0.y;
                o1.x += r1.x; o1.y += r1.y;
            }
            *(float2*)(C + (size_t)m0*N + n)     = o0;
            *(float2*)(C + (size_t)(m0+8)*N + n) = o1;
        }
    }
}

// ---------------- 3. RoPE + gates + head transpose (tf32 pre-round) ----------------
__global__ void rope_gate_kernel(const float* __restrict__ qg,
                                 const float* __restrict__ kg,
                                 const float* __restrict__ vg)
{
    int tid = blockIdx.x * blockDim.x + threadIdx.x;
    int d  = tid & 31;
    int hh = (tid >> 5) & 15;
    int l  = (tid >> 9) & 2047;
    int b  = tid >> 20;
    if (b >= NB) return;
    size_t row   = (size_t)b*NL + l;
    size_t hbase = row * HID;
    float p   = g_pos[row];
    float inv = expf(-(float)d * (9.210340371976184f / 32.0f));
    float fr  = p * inv;
    float sn, cs;
    sincosf(fr, &sn, &cs);
    size_t ob = (((size_t)b*NH + hh)*NL + l)*NDH;
    {
        float2 e = *(const float2*)(&g_h[hbase + 2*ND + hh*NDH + 2*d]);
        float gq = qg[row*NH + hh];
        g_q[ob + d]      = tf32_rnd((e.x*cs - e.y*sn) * gq);
        g_q[ob + d + 32] = tf32_rnd((e.x*sn + e.y*cs) * gq);
    }
    {
        float2 e = *(const float2*)(&g_h[hbase + 3*ND + hh*NDH + 2*d]);
        float gk = kg[row*NH + hh];
        g_k[ob + d]      = tf32_rnd((e.x*cs - e.y*sn) * gk);
        g_k[ob + d + 32] = tf32_rnd((e.x*sn + e.y*cs) * gk);
    }
    {
        float gv = vg[row*NH + hh];
        g_v[ob + d]      = tf32_rnd(g_h[hbase + ND + hh*NDH + d]      * gv);
        g_v[ob + d + 32] = tf32_rnd(g_h[hbase + ND + hh*NDH + d + 32] * gv);
    }
}

// ---------------- 4. tf32 mma attention (R14 + V half-preload) ----------------
// CTA: 64 q-rows for one (b,h); 8 warps. 4-slot KV ring, 3-ahead prefetch.
// QK^T: warp w -> m-rows (w>>1)*16, key-half (w&1)*16. Q frags in regs.
// S@V : same m-rows, d-half (w&1)*32. Pair-scoped S barrier.
// V fragments for ks=0,1 preloaded before the QK loop (overlap mma latency).
#define AST 68
#define SST 36
#define ABK 32
#define A_KV_F (2*ABK*AST)                 // floats per KV slot
#define A_QS_F (64*AST)                    // Q region (>= 64*SST S region)
#define A_SMEM_BYTES ((A_QS_F + 4*A_KV_F)*4)   // 87040

__global__ void __launch_bounds__(256, 2)
attn_mma(const float* __restrict__ bias, const float* __restrict__ head_scale)
{
    extern __shared__ float sm[];
    float* Qs = sm;                    // [64][AST], later reused as Ss [64][SST]
    float* Ss = sm;
    float* KV = sm + A_QS_F;           // [4][{K,V}][ABK][AST]

    const int ib = (int)gridDim.x - 1 - (int)blockIdx.x;   // big tiles first
    const int bh = blockIdx.y;
    const int b  = bh >> 4, hh = bh & 15;
    const int tid = threadIdx.x, lane = tid & 31, wid = tid >> 5;
    const int g = lane >> 2, t = lane & 3;
    const int r0 = (wid >> 1) * 16;        // warp m-rows
    const int kh = (wid & 1);              // key-half / d-half selector
    const int pair_bar = 1 + (wid >> 1);   // named barrier per warp pair

    const int njb = 2*(ib + 1);

    auto load_kv = [&](int slot, int jb){
        if (jb < njb){
            float* Ks = KV + slot*A_KV_F;
            float* Vs = Ks + ABK*AST;
            const float* kp = g_k + ((size_t)bh*NL + (size_t)jb*ABK)*NDH;
            const float* vp = g_v + ((size_t)bh*NL + (size_t)jb*ABK)*NDH;
            #pragma unroll
            for (int it = 0; it < 4; it++){
                int idx = tid + it*256;      // 0..1023
                int isV = idx >> 9;
                int li  = idx & 511;
                int row = li >> 4;
                int c16 = li & 15;
                float* dst = (isV ? Vs : Ks) + row*AST + c16*4;
                const float* src = (isV ? vp : kp) + row*64 + c16*4;
                cp_async16(smem_u32(dst), src);
            }
        }
        CP_COMMIT();
    };

    {   // group 0: Q tile (64 rows x 16 chunks)
        const float* qp = g_q + ((size_t)bh*NL + (size_t)ib*64)*NDH;
        #pragma unroll
        for (int it = 0; it < 4; it++){
            int idx = tid + it*256;
            int row = idx >> 4;
            int c16 = idx & 15;
            cp_async16(smem_u32(Qs + row*AST + c16*4), qp + row*64 + c16*4);
        }
        CP_COMMIT();
    }
    load_kv(0, 0);      // group 1
    load_kv(1, 1);      // group 2
    load_kv(2, 2);      // group 3

    // wait for Q (group0) + slot0 (group1); hoist Q fragments to registers
    CP_WAIT(2);
    __syncthreads();
    uint32_t Qa[8][4];
    {
        const float* qw = Qs + (r0 + g)*AST + t;
        #pragma unroll
        for (int ks = 0; ks < 8; ks++){
            Qa[ks][0] = __float_as_uint(qw[ks*8]);
            Qa[ks][1] = __float_as_uint(qw[8*AST + ks*8]);
            Qa[ks][2] = __float_as_uint(qw[ks*8 + 4]);
            Qa[ks][3] = __float_as_uint(qw[8*AST + ks*8 + 4]);
        }
    }
    __syncthreads();    // all warps done reading Q before S region reuse

    const float scale = head_scale[hh];
    float Yc[4][4];
    #pragma unroll
    for (int j = 0; j < 4; j++)
        #pragma unroll
        for (int c = 0; c < 4; c++) Yc[j][c] = 0.0f;

    const int ig0 = ib*64 + r0 + g;

    for (int jb = 0; jb < njb; ++jb){
        int slot = jb & 3;
        CP_WAIT(2);
        __syncthreads();                       // slot ready; prev iter fully done
        load_kv((jb + 3) & 3, jb + 3);         // refill (empty commit if beyond)

        // bias prefetch (latency hidden under QK mma loop)
        float2 pb0[2], pb1[2];
        {
            const float* bp = bias + ((size_t)b*NL + ig0)*NL + jb*ABK + kh*16 + 2*t;
            #pragma unroll
            for (int nf = 0; nf < 2; nf++){
                pb0[nf] = *(const float2*)(bp + nf*8);
                pb1[nf] = *(const float2*)(bp + nf*8 + (size_t)8*NL);
            }
        }

        const float* Ksb = KV + slot*A_KV_F;
        const float* Vsb = Ksb + ABK*AST;

        // V fragment half-preload (ks=0,1): independent of S, overlaps QK mma latency
        uint32_t Vf[2][4][2];
        #pragma unroll
        for (int ks = 0; ks < 2; ks++)
            #pragma unroll
            for (int nf = 0; nf < 4; nf++){
                int dc = kh*32 + nf*8 + g;
                Vf[ks][nf][0] = __float_as_uint(Vsb[(ks*8 + t)*AST + dc]);
                Vf[ks][nf][1] = __float_as_uint(Vsb[(ks*8 + t + 4)*AST + dc]);
            }

        // ---- S = Q @ K^T  (keys kh*16 .. kh*16+15) ----
        float Sc[2][4];
        #pragma unroll
        for (int nf = 0; nf < 2; nf++)
            #pragma unroll
            for (int c = 0; c < 4; c++) Sc[nf][c] = 0.0f;

        const float* Bw = Ksb + (kh*16 + g)*AST + t;
        #pragma unroll
        for (int ks = 0; ks < 8; ks++){
            #pragma unroll
            for (int nf = 0; nf < 2; nf++){
                uint32_t bf[2];
                bf[0] = __float_as_uint(Bw[nf*8*AST + ks*8]);
                bf[1] = __float_as_uint(Bw[nf*8*AST + ks*8 + 4]);
                MMA16N8K8(Sc[nf], Qa[ks], bf);
            }
        }

        // ---- epilogue: scale + 4*bias + fast silu + causal -> Ss ----
        #pragma unroll
        for (int nf = 0; nf < 2; nf++){
            int lc = kh*16 + nf*8 + 2*t;
            int jg = jb*ABK + lc;
            float z00 = silu_f(fmaf(Sc[nf][0], scale, 4.0f*pb0[nf].x));
            float z01 = silu_f(fmaf(Sc[nf][1], scale, 4.0f*pb0[nf].y));
            float z10 = silu_f(fmaf(Sc[nf][2], scale, 4.0f*pb1[nf].x));
            float z11 = silu_f(fmaf(Sc[nf][3], scale, 4.0f*pb1[nf].y));
            if (jg     > ig0    ) z00 = 0.0f;
            if (jg + 1 > ig0    ) z01 = 0.0f;
            if (jg     > ig0 + 8) z10 = 0.0f;
            if (jg + 1 > ig0 + 8) z11 = 0.0f;
            float2 s0, s1;
            s0.x = tf32_rnd(z00); s0.y = tf32_rnd(z01);
            s1.x = tf32_rnd(z10); s1.y = tf32_rnd(z11);
            *(float2*)&Ss[(r0+g)*SST + lc]   = s0;
            *(float2*)&Ss[(r0+8+g)*SST + lc] = s1;
        }
        // pair-scoped barrier: only the 2 warps sharing rows r0..r0+15 exchange S
        asm volatile("bar.sync %0, %1;" :: "r"(pair_bar), "r"(64) : "memory");

        // ---- Y += S @ V  (d-cols kh*32 .. kh*32+31) ----
        const float* Aw2 = Ss + (r0 + g)*SST + t;
        #pragma unroll
        for (int ks = 0; ks < 4; ks++){
            uint32_t a[4];
            a[0] = __float_as_uint(Aw2[ks*8]);
            a[1] = __float_as_uint(Aw2[8*SST + ks*8]);
            a[2] = __float_as_uint(Aw2[ks*8 + 4]);
            a[3] = __float_as_uint(Aw2[8*SST + ks*8 + 4]);
            if (ks < 2){
                #pragma unroll
                for (int nf = 0; nf < 4; nf++)
                    MMA16N8K8(Yc[nf], a, Vf[ks][nf]);
            } else {
                #pragma unroll
                for (int nf = 0; nf < 4; nf++){
                    int dc = kh*32 + nf*8 + g;
                    uint32_t bf[2];
                    bf[0] = __float_as_uint(Vsb[(ks*8 + t)*AST + dc]);
                    bf[1] = __float_as_uint(Vsb[(ks*8 + t + 4)*AST + dc]);
                    MMA16N8K8(Yc[nf], a, bf);
                }
            }
        }
    }

    // ---- final: ym = Y * u ----
    {
        int l = ib*64 + r0 + g;
        size_t row0 = (size_t)b*NL + l;
        #pragma unroll
        for (int nf = 0; nf < 4; nf++){
            int d0 = kh*32 + nf*8 + 2*t;
            float2 u0 = *(const float2*)&g_h[row0*HID + hh*NDH + d0];
            float2 u1 = *(const float2*)&g_h[(row0+8)*HID + hh*NDH + d0];
            float2 o0, o1;
            o0.x = Yc[nf][0]*u0.x; o0.y = Yc[nf][1]*u0.y;
            o1.x = Yc[nf][2]*u1.x; o1.y = Yc[nf][3]*u1.y;
            *(float2*)&g_ym[row0*ND + hh*NDH + d0]     = o0;
            *(float2*)&g_ym[(row0+8)*ND + hh*NDH + d0] = o1;
        }
    }
}

// ---------------- 6. LayerNorm ----------------
__global__ void ln_kernel(const float* __restrict__ z, const float* __restrict__ gamma,
                          const float* __restrict__ beta, float* __restrict__ out)
{
    __shared__ float rs[8], rq[8], mv[2];
    int row = blockIdx.x;
    int t = threadIdx.x;
    const float4* zr = (const float4*)(z + (size_t)row * ND);
    float4 v = zr[t];
    float s  = v.x + v.y + v.z + v.w;
    float sq = v.x*v.x + v.y*v.y + v.z*v.z + v.w*v.w;
    #pragma unroll
    for (int o = 16; o; o >>= 1){
        s  += __shfl_down_sync(0xffffffffu, s,  o);
        sq += __shfl_down_sync(0xffffffffu, sq, o);
    }
    if ((t & 31) == 0){ rs[t>>5] = s; rq[t>>5] = sq; }
    __syncthreads();
    if (t == 0){
        float S = 0.f, Q = 0.f;
        #pragma unroll
        for (int i = 0; i < 8; i++){ S += rs[i]; Q += rq[i]; }
        float mean = S * (1.0f/ND);
        float var  = Q * (1.0f/ND) - mean*mean;
        mv[0] = mean; mv[1] = rsqrtf(var + 1e-5f);
    }
    __syncthreads();
    float mean = mv[0], rstd = mv[1];
    float4 g  = ((const float4*)gamma)[t];
    float4 be = ((const float4*)beta )[t];
    float4 o;
    o.x = (v.x - mean)*rstd*g.x + be.x;
    o.y = (v.y - mean)*rstd*g.y + be.y;
    o.z = (v.z - mean)*rstd*g.z + be.z;
    o.w = (v.w - mean)*rstd*g.w + be.w;
    ((float4*)(out + (size_t)row * ND))[t] = o;
}

// ---------------- launch ----------------
extern "C" void kernel_launch(void* const* d_in, const int* in_sizes, int n_in,
                              void* d_out, int out_size)
{
    const float* x   = (const float*)d_in[0];
    const float* rl  = (const float*)d_in[3];
    const float* qg  = (const float*)d_in[4];
    const float* kg  = (const float*)d_in[5];
    const float* vg  = (const float*)d_in[6];
    const float* tpb = (const float*)d_in[7];
    const float* pw  = (const float*)d_in[8];
    const float* pb  = (const float*)d_in[9];
    const float* ow  = (const float*)d_in[10];
    const float* ob  = (const float*)d_in[11];
    const float* hs  = (const float*)d_in[12];
    const float* lg  = (const float*)d_in[13];
    const float* lb  = (const float*)d_in[14];
    float* out = (float*)d_out;

    float *hp, *ymp, *zp;
    cudaGetSymbolAddress((void**)&hp,  g_h);
    cudaGetSymbolAddress((void**)&ymp, g_ym);
    cudaGetSymbolAddress((void**)&zp,  g_z);

    cudaFuncSetAttribute(gemm_mma<0>, cudaFuncAttributeMaxDynamicSharedMemorySize, G_SMEM_BYTES);
    cudaFuncSetAttribute(gemm_mma<1>, cudaFuncAttributeMaxDynamicSharedMemorySize, G_SMEM_BYTES);
    cudaFuncSetAttribute(attn_mma,    cudaFuncAttributeMaxDynamicSharedMemorySize, A_SMEM_BYTES);

    // 1. positions
    cumsum_kernel<<<NB, 1024>>>(rl);

    // 2. h = silu(x @ proj_w^T + proj_b)   [tf32 mma]
    gemm_mma<0><<<dim3(HID/128, MROWS/128), 256, G_SMEM_BYTES>>>(x, pw, pb, nullptr, hp, HID, ND);

    // 3. rope + gates + head transpose (+ tf32 pre-round of q/k/v)
    rope_gate_kernel<<<(NB*NL*NH*32)/256, 256>>>(qg, kg, vg);

    // 4. fused attention + u-gate   [tf32 mma]
    attn_mma<<<dim3(NL/64, NB*NH), 256, A_SMEM_BYTES>>>(tpb, hs);

    // 5. z = ym @ out_w^T + out_b + x   [tf32 mma]
    gemm_mma<1><<<dim3(ND/128, MROWS/128), 256, G_SMEM_BYTES>>>(ymp, ow, ob, x, zp, ND, ND);

    // 6. layernorm
    ln_kernel<<<MROWS, 256>>>(zp, lg, lb, out);
}

// round 16
// speedup vs baseline: 1.5971x; 1.0908x over previous
#include <cuda_runtime.h>
#include <math.h>
#include <stdint.h>

#define NB 2
#define NL 2048
#define ND 1024
#define NH 16
#define NDH 64
#define MROWS (NB*NL)   // 4096
#define HID (4*ND)      // 4096

// ---------------- scratch ----------------
__device__ float g_h  [(size_t)MROWS * HID];
__device__ float g_q  [(size_t)NB*NH*NL*NDH];   // fragment-major (see rope_gate)
__device__ float g_k  [(size_t)NB*NH*NL*NDH];   // fragment-major
__device__ float g_v  [(size_t)NB*NH*NL*NDH];   // fragment-major
__device__ float g_ym [(size_t)MROWS * ND];
__device__ float g_z  [(size_t)MROWS * ND];
__device__ float g_pos[NB*NL];

// fast silu
__device__ __forceinline__ float silu_f(float x){
    return __fdividef(x, 1.0f + __expf(-x));
}

__device__ __forceinline__ uint32_t tf32_bits(float x){
    uint32_t u; asm("cvt.rna.tf32.f32 %0, %1;" : "=r"(u) : "f"(x));
    return u;
}
__device__ __forceinline__ float tf32_rnd(float x){ return __uint_as_float(tf32_bits(x)); }

__device__ __forceinline__ uint32_t smem_u32(const void* p){
    uint32_t a;
    asm("{ .reg .u64 t; cvta.to.shared.u64 t, %1; cvt.u32.u64 %0, t; }" : "=r"(a) : "l"(p));
    return a;
}
__device__ __forceinline__ void cp_async16(uint32_t saddr, const void* g){
    asm volatile("cp.async.cg.shared.global [%0], [%1], 16;" :: "r"(saddr), "l"(g));
}
#define CP_COMMIT()  asm volatile("cp.async.commit_group;" ::: "memory")
#define CP_WAIT(n)   asm volatile("cp.async.wait_group %0;" :: "n"(n) : "memory")

#define MMA16N8K8(c, a, b) \
    asm volatile("mma.sync.aligned.m16n8k8.row.col.f32.tf32.tf32.f32 " \
        "{%0,%1,%2,%3}, {%4,%5,%6,%7}, {%8,%9}, {%0,%1,%2,%3};" \
        : "+f"((c)[0]), "+f"((c)[1]), "+f"((c)[2]), "+f"((c)[3]) \
        : "r"((a)[0]), "r"((a)[1]), "r"((a)[2]), "r"((a)[3]), \
          "r"((b)[0]), "r"((b)[1]))

// ---------------- 1. cumsum of rope_lambda -> g_pos ----------------
__global__ void cumsum_kernel(const float* __restrict__ rl)
{
    __shared__ float s[1024];
    int b = blockIdx.x, t = threadIdx.x;
    const float* a = rl + (size_t)b * NL;
    float x0 = a[2*t], x1 = a[2*t+1];
    float sum = x0 + x1;
    s[t] = sum;
    __syncthreads();
    for (int off = 1; off < 1024; off <<= 1){
        float v = (t >= off) ? s[t-off] : 0.0f;
        __syncthreads();
        s[t] += v;
        __syncthreads();
    }
    float incl = s[t];
    g_pos[b*NL + 2*t]     = incl - x1;
    g_pos[b*NL + 2*t + 1] = incl;
}

// ---------------- 2/5. tf32 mma.sync GEMM (NT), 3-stage (unchanged) ----------------
#define GSTAGES 3
#define GKC 32
#define G_STRIDE 36
#define G_TILE_F (128*G_STRIDE)
#define G_TILE_B (G_TILE_F*4)
#define G_SMEM_BYTES (GSTAGES * 2 * G_TILE_B)   // 110592

template<int EPI>
__global__ void __launch_bounds__(256, 2)
gemm_mma(const float* __restrict__ A, const float* __restrict__ Bw,
         const float* __restrict__ bias, const float* __restrict__ resid,
         float* __restrict__ C, int N, int K)
{
    extern __shared__ float dsm[];
    const uint32_t sb = smem_u32(dsm);
    const int tid  = threadIdx.x;
    const int lane = tid & 31, wid = tid >> 5;
    const int wm = wid >> 2, wn = wid & 3;
    const int g  = lane >> 2, t = lane & 3;
    const int bn = blockIdx.x * 128;
    const int bm = blockIdx.y * 128;

    float acc[4][4][4];
    #pragma unroll
    for (int i = 0; i < 4; i++)
        #pragma unroll
        for (int j = 0; j < 4; j++)
            #pragma unroll
            for (int c = 0; c < 4; c++) acc[i][j][c] = 0.0f;

    auto load_stage = [&](int s, int kt){
        uint32_t base = sb + (uint32_t)s * (2*G_TILE_B);
        #pragma unroll
        for (int it = 0; it < 8; it++){
            int idx = tid + it*256;
            int isB = idx >> 10;
            int li  = idx & 1023;
            int row = li >> 3;
            int c16 = li & 7;
            const float* src = (isB ? (Bw + (size_t)(bn+row)*K)
                                    : (A  + (size_t)(bm+row)*K)) + kt + c16*4;
            cp_async16(base + (uint32_t)isB*G_TILE_B + (uint32_t)(row*144 + c16*16), src);
        }
        CP_COMMIT();
    };

    #pragma unroll
    for (int s = 0; s < GSTAGES; s++) load_stage(s, s*GKC);

    const int NCH = K / GKC;
    int s = 0;
    for (int ch = 0; ch < NCH; ch++){
        CP_WAIT(GSTAGES-1);
        __syncthreads();

        const float* As = dsm + (size_t)s*2*G_TILE_F;
        const float* Bs = As + G_TILE_F;
        const float* Awp = As + (wm*64 + g)*G_STRIDE + t;
        const float* Bwp = Bs + (wn*32 + g)*G_STRIDE + t;

        #pragma unroll
        for (int ks = 0; ks < 4; ks++){
            int k0 = ks*8;
            uint32_t b[4][2];
            #pragma unroll
            for (int fj = 0; fj < 4; fj++){
                const float* bp = Bwp + fj*8*G_STRIDE + k0;
                b[fj][0] = tf32_bits(bp[0]);
                b[fj][1] = tf32_bits(bp[4]);
            }
            #pragma unroll
            for (int fi = 0; fi < 4; fi++){
                const float* ap = Awp + fi*16*G_STRIDE + k0;
                uint32_t a[4];
                a[0] = tf32_bits(ap[0]);
                a[1] = tf32_bits(ap[8*G_STRIDE]);
                a[2] = tf32_bits(ap[4]);
                a[3] = tf32_bits(ap[8*G_STRIDE+4]);
                #pragma unroll
                for (int fj = 0; fj < 4; fj++)
                    MMA16N8K8(acc[fi][fj], a, b[fj]);
            }
        }
        __syncthreads();
        if (ch + GSTAGES < NCH) load_stage(s, (ch + GSTAGES)*GKC);
        if (++s == GSTAGES) s = 0;
    }

    #pragma unroll
    for (int fi = 0; fi < 4; fi++){
        int m0 = bm + wm*64 + fi*16 + g;
        #pragma unroll
        for (int fj = 0; fj < 4; fj++){
            int n = bn + wn*32 + fj*8 + 2*t;
            float2 bv = *(const float2*)(bias + n);
            float2 o0, o1;
            o0.x = acc[fi][fj][0] + bv.x; o0.y = acc[fi][fj][1] + bv.y;
            o1.x = acc[fi][fj][2] + bv.x; o1.y = acc[fi][fj][3] + bv.y;
            if (EPI == 0){
                o0.x = silu_f(o0.x); o0.y = silu_f(o0.y);
                o1.x = silu_f(o1.x); o1.y = silu_f(o1.y);
            } else {
                float2 r0 = *(const float2*)(resid + (size_t)m0*N + n);
                float2 r1 = *(const float2*)(resid + (size_t)(m0+8)*N + n);
                o0.x += r0.x; o0.y += r0.y;
                o1.x += r1.x; o1.y += r1.y;
            }
            *(float2*)(C + (size_t)m0*N + n)     = o0;
            *(float2*)(C + (size_t)(m0+8)*N + n) = o1;
        }
    }
}

// ---------------- fragment-major address helpers ----------------
// Q: [bh][row/16][ks(8)][lane(32)][slot(4)]; slot = ((dd&7)>>2)*2 + ((row&15)>>3)
//    lane = (row&7)*4 + (dd&3); Qa pack {a0,a1,a2,a3}
__device__ __forceinline__ size_t q_addr(int bh, int row, int dd){
    int rowblk = row >> 4;
    int ks = dd >> 3;
    int lane = ((row & 7) << 2) + (dd & 3);
    int slot = (((dd & 7) >> 2) << 1) + ((row & 15) >> 3);
    return ((size_t)bh*(NL>>4) + rowblk)*1024 + ks*128 + lane*4 + slot;
}
// K: [bh][key/32][kspair(4)][kt(4)][lane(32)][slot(4)]
//    slot = ((dd>>3)&1)*2 + ((dd&7)>>2); pack {bf0(ks even),bf1(even),bf0(odd),bf1(odd)}
__device__ __forceinline__ size_t k_addr(int bh, int key, int dd){
    int jb = key >> 5;
    int kt = (key & 31) >> 3;
    int p  = dd >> 4;
    int lane = ((key & 7) << 2) + (dd & 3);
    int slot = (((dd >> 3) & 1) << 1) + ((dd & 7) >> 2);
    return ((size_t)bh*(NL>>5) + jb)*2048 + p*512 + kt*128 + lane*4 + slot;
}
// V: [bh][key/32][kspair(2)][nfg(8)][lane(32)][slot(4)]
//    slot = (key&15)>>2; lane = (dd&7)*4 + (key&3)
__device__ __forceinline__ size_t v_addr(int bh, int key, int dd){
    int jb = key >> 5;
    int p  = (key & 31) >> 4;
    int nfg = dd >> 3;
    int lane = ((dd & 7) << 2) + (key & 3);
    int slot = (key & 15) >> 2;
    return ((size_t)bh*(NL>>5) + jb)*2048 + p*1024 + nfg*128 + lane*4 + slot;
}

// ---------------- 3. RoPE + gates -> fragment-major q/k/v ----------------
__global__ void rope_gate_kernel(const float* __restrict__ qg,
                                 const float* __restrict__ kg,
                                 const float* __restrict__ vg)
{
    int tid = blockIdx.x * blockDim.x + threadIdx.x;
    int d  = tid & 31;
    int hh = (tid >> 5) & 15;
    int l  = (tid >> 9) & 2047;
    int b  = tid >> 20;
    if (b >= NB) return;
    size_t row   = (size_t)b*NL + l;
    size_t hbase = row * HID;
    int bh = b*NH + hh;
    float p   = g_pos[row];
    float inv = expf(-(float)d * (9.210340371976184f / 32.0f));
    float fr  = p * inv;
    float sn, cs;
    sincosf(fr, &sn, &cs);
    {
        float2 e = *(const float2*)(&g_h[hbase + 2*ND + hh*NDH + 2*d]);
        float gq = qg[row*NH + hh];
        g_q[q_addr(bh, l, d)]      = tf32_rnd((e.x*cs - e.y*sn) * gq);
        g_q[q_addr(bh, l, d + 32)] = tf32_rnd((e.x*sn + e.y*cs) * gq);
    }
    {
        float2 e = *(const float2*)(&g_h[hbase + 3*ND + hh*NDH + 2*d]);
        float gk = kg[row*NH + hh];
        g_k[k_addr(bh, l, d)]      = tf32_rnd((e.x*cs - e.y*sn) * gk);
        g_k[k_addr(bh, l, d + 32)] = tf32_rnd((e.x*sn + e.y*cs) * gk);
    }
    {
        float gv = vg[row*NH + hh];
        g_v[v_addr(bh, l, d)]      = tf32_rnd(g_h[hbase + ND + hh*NDH + d]      * gv);
        g_v[v_addr(bh, l, d + 32)] = tf32_rnd(g_h[hbase + ND + hh*NDH + d + 32] * gv);
    }
}

// ---------------- 4. tf32 mma attention: fragment-major LDS.128 loads ----------------
// CTA: 64 q-rows for one (b,h); 8 warps. 4-slot KV ring, 3-ahead prefetch.
// QK^T: warp w -> m-rows (w>>1)*16, key-half (w&1)*16. Q frags in regs (LDS.128 hoist).
// S@V : same m-rows, d-half (w&1)*32. Pair-scoped S barrier. V/K frags via LDS.128.
#define SST 36
#define ABK 32
#define A_KV_F 4096                        // floats per KV slot (K 2048 + V 2048)
#define A_QS_F 4096                        // Q region (>= 64*SST for S reuse)
#define A_SMEM_BYTES ((A_QS_F + 4*A_KV_F)*4)   // 81920

__global__ void __launch_bounds__(256, 2)
attn_mma(const float* __restrict__ bias, const float* __restrict__ head_scale)
{
    extern __shared__ float sm[];
    float* Qs = sm;                    // [4096] frag-major, reused as Ss [64][SST]
    float* Ss = sm;
    float* KV = sm + A_QS_F;           // [4][K 2048 | V 2048]

    const int ib = (int)gridDim.x - 1 - (int)blockIdx.x;   // big tiles first
    const int bh = blockIdx.y;
    const int b  = bh >> 4, hh = bh & 15;
    const int tid = threadIdx.x, lane = tid & 31, wid = tid >> 5;
    const int g = lane >> 2, t = lane & 3;
    const int r0 = (wid >> 1) * 16;        // warp m-rows
    const int rb = (wid >> 1);             // row block 0..3
    const int kh = (wid & 1);              // key-half / d-half selector
    const int pair_bar = 1 + (wid >> 1);   // named barrier per warp pair

    const int njb = 2*(ib + 1);

    auto load_kv = [&](int slot, int jb){
        if (jb < njb){
            float* dstK = KV + slot*A_KV_F;
            const float* srcK = g_k + ((size_t)bh*(NL>>5) + jb)*2048;
            const float* srcV = g_v + ((size_t)bh*(NL>>5) + jb)*2048;
            #pragma unroll
            for (int it = 0; it < 4; it++){
                int idx = tid + it*256;      // 0..1023 chunks
                int isV = idx >> 9;
                int li  = idx & 511;
                const float* src = (isV ? srcV : srcK) + li*4;
                cp_async16(smem_u32(dstK + isV*2048 + li*4), src);
            }
        }
        CP_COMMIT();
    };

    {   // group 0: Q tile (4096 floats, linear frag-major)
        const float* qp = g_q + ((size_t)bh*(NL>>4) + (size_t)ib*4)*1024;
        #pragma unroll
        for (int it = 0; it < 4; it++){
            int idx = tid + it*256;
            cp_async16(smem_u32(Qs + idx*4), qp + idx*4);
        }
        CP_COMMIT();
    }
    load_kv(0, 0);      // group 1
    load_kv(1, 1);      // group 2
    load_kv(2, 2);      // group 3

    // wait for Q (group0) + slot0 (group1); hoist Q fragments (8 x LDS.128)
    CP_WAIT(2);
    __syncthreads();
    uint32_t Qa[8][4];
    #pragma unroll
    for (int ks = 0; ks < 8; ks++){
        float4 qv = *(const float4*)&Qs[rb*1024 + ks*128 + lane*4];
        Qa[ks][0] = __float_as_uint(qv.x);
        Qa[ks][1] = __float_as_uint(qv.y);
        Qa[ks][2] = __float_as_uint(qv.z);
        Qa[ks][3] = __float_as_uint(qv.w);
    }
    __syncthreads();    // all warps done reading Q before S region reuse

    const float scale = head_scale[hh];
    float Yc[4][4];
    #pragma unroll
    for (int j = 0; j < 4; j++)
        #pragma unroll
        for (int c = 0; c < 4; c++) Yc[j][c] = 0.0f;

    const int ig0 = ib*64 + r0 + g;

    for (int jb = 0; jb < njb; ++jb){
        int slot = jb & 3;
        CP_WAIT(2);
        __syncthreads();                       // slot ready; prev iter fully done
        load_kv((jb + 3) & 3, jb + 3);         // refill (empty commit if beyond)

        // bias prefetch (latency hidden under QK mma loop)
        float2 pb0[2], pb1[2];
        {
            const float* bp = bias + ((size_t)b*NL + ig0)*NL + jb*ABK + kh*16 + 2*t;
            #pragma unroll
            for (int nf = 0; nf < 2; nf++){
                pb0[nf] = *(const float2*)(bp + nf*8);
                pb1[nf] = *(const float2*)(bp + nf*8 + (size_t)8*NL);
            }
        }

        const float* Ksb = KV + slot*A_KV_F;
        const float* Vsb = Ksb + 2048;

        // V fragment preload p=0 (ks 0,1): 4 x LDS.128, overlaps QK mma latency
        float4 Vp[4];
        #pragma unroll
        for (int nf = 0; nf < 4; nf++)
            Vp[nf] = *(const float4*)&Vsb[(kh*4 + nf)*128 + lane*4];

        // ---- S = Q @ K^T  (keys kh*16 .. kh*16+15), K frags via LDS.128 ----
        float Sc[2][4];
        #pragma unroll
        for (int nf = 0; nf < 2; nf++)
            #pragma unroll
            for (int c = 0; c < 4; c++) Sc[nf][c] = 0.0f;

        #pragma unroll
        for (int p = 0; p < 4; p++){
            float4 k0 = *(const float4*)&Ksb[p*512 + (kh*2 + 0)*128 + lane*4];
            float4 k1 = *(const float4*)&Ksb[p*512 + (kh*2 + 1)*128 + lane*4];
            uint32_t bf[2];
            bf[0] = __float_as_uint(k0.x); bf[1] = __float_as_uint(k0.y);
            MMA16N8K8(Sc[0], Qa[2*p], bf);
            bf[0] = __float_as_uint(k1.x); bf[1] = __float_as_uint(k1.y);
            MMA16N8K8(Sc[1], Qa[2*p], bf);
            bf[0] = __float_as_uint(k0.z); bf[1] = __float_as_uint(k0.w);
            MMA16N8K8(Sc[0], Qa[2*p+1], bf);
            bf[0] = __float_as_uint(k1.z); bf[1] = __float_as_uint(k1.w);
            MMA16N8K8(Sc[1], Qa[2*p+1], bf);
        }

        // ---- epilogue: scale + 4*bias + fast silu + causal -> Ss ----
        #pragma unroll
        for (int nf = 0; nf < 2; nf++){
            int lc = kh*16 + nf*8 + 2*t;
            int jg = jb*ABK + lc;
            float z00 = silu_f(fmaf(Sc[nf][0], scale, 4.0f*pb0[nf].x));
            float z01 = silu_f(fmaf(Sc[nf][1], scale, 4.0f*pb0[nf].y));
            float z10 = silu_f(fmaf(Sc[nf][2], scale, 4.0f*pb1[nf].x));
            float z11 = silu_f(fmaf(Sc[nf][3], scale, 4.0f*pb1[nf].y));
            if (jg     > ig0    ) z00 = 0.0f;
            if (jg + 1 > ig0    ) z01 = 0.0f;
            if (jg     > ig0 + 8) z10 = 0.0f;
            if (jg + 1 > ig0 + 8) z11 = 0.0f;
            float2 s0, s1;
            s0.x = tf32_rnd(z00); s0.y = tf32_rnd(z01);
            s1.x = tf32_rnd(z10); s1.y = tf32_rnd(z11);
            *(float2*)&Ss[(r0+g)*SST + lc]   = s0;
            *(float2*)&Ss[(r0+8+g)*SST + lc] = s1;
        }
        // pair-scoped barrier: only the 2 warps sharing rows r0..r0+15 exchange S
        asm volatile("bar.sync %0, %1;" :: "r"(pair_bar), "r"(64) : "memory");

        // ---- Y += S @ V  (d-cols kh*32 .. kh*32+31), V frags via LDS.128 ----
        const float* Aw2 = Ss + (r0 + g)*SST + t;
        #pragma unroll
        for (int p = 0; p < 2; p++){
            float4 Vf[4];
            if (p == 0){
                #pragma unroll
                for (int nf = 0; nf < 4; nf++) Vf[nf] = Vp[nf];
            } else {
                #pragma unroll
                for (int nf = 0; nf < 4; nf++)
                    Vf[nf] = *(const float4*)&Vsb[1024 + (kh*4 + nf)*128 + lane*4];
            }
            #pragma unroll
            for (int sub = 0; sub < 2; sub++){
                int ks = 2*p + sub;
                uint32_t a[4];
                a[0] = __float_as_uint(Aw2[ks*8]);
                a[1] = __float_as_uint(Aw2[8*SST + ks*8]);
                a[2] = __float_as_uint(Aw2[ks*8 + 4]);
                a[3] = __float_as_uint(Aw2[8*SST + ks*8 + 4]);
                #pragma unroll
                for (int nf = 0; nf < 4; nf++){
                    uint32_t bf[2];
                    if (sub == 0){
                        bf[0] = __float_as_uint(Vf[nf].x);
                        bf[1] = __float_as_uint(Vf[nf].y);
                    } else {
                        bf[0] = __float_as_uint(Vf[nf].z);
                        bf[1] = __float_as_uint(Vf[nf].w);
                    }
                    MMA16N8K8(Yc[nf], a, bf);
                }
            }
        }
    }

    // ---- final: ym = Y * u ----
    {
        int l = ib*64 + r0 + g;
        size_t row0 = (size_t)b*NL + l;
        #pragma unroll
        for (int nf = 0; nf < 4; nf++){
            int d0 = kh*32 + nf*8 + 2*t;
            float2 u0 = *(const float2*)&g_h[row0*HID + hh*NDH + d0];
            float2 u1 = *(const float2*)&g_h[(row0+8)*HID + hh*NDH + d0];
            float2 o0, o1;
            o0.x = Yc[nf][0]*u0.x; o0.y = Yc[nf][1]*u0.y;
            o1.x = Yc[nf][2]*u1.x; o1.y = Yc[nf][3]*u1.y;
            *(float2*)&g_ym[row0*ND + hh*NDH + d0]     = o0;
            *(float2*)&g_ym[(row0+8)*ND + hh*NDH + d0] = o1;
        }
    }
}

// ---------------- 6. LayerNorm ----------------
__global__ void ln_kernel(const float* __restrict__ z, const float* __restrict__ gamma,
                          const float* __restrict__ beta, float* __restrict__ out)
{
    __shared__ float rs[8], rq[8], mv[2];
    int row = blockIdx.x;
    int t = threadIdx.x;
    const float4* zr = (const float4*)(z + (size_t)row * ND);
    float4 v = zr[t];
    float s  = v.x + v.y + v.z + v.w;
    float sq = v.x*v.x + v.y*v.y + v.z*v.z + v.w*v.w;
    #pragma unroll
    for (int o = 16; o; o >>= 1){
        s  += __shfl_down_sync(0xffffffffu, s,  o);
        sq += __shfl_down_sync(0xffffffffu, sq, o);
    }
    if ((t & 31) == 0){ rs[t>>5] = s; rq[t>>5] = sq; }
    __syncthreads();
    if (t == 0){
        float S = 0.f, Q = 0.f;
        #pragma unroll
        for (int i = 0; i < 8; i++){ S += rs[i]; Q += rq[i]; }
        float mean = S * (1.0f/ND);
        float var  = Q * (1.0f/ND) - mean*mean;
        mv[0] = mean; mv[1] = rsqrtf(var + 1e-5f);
    }
    __syncthreads();
    float mean = mv[0], rstd = mv[1];
    float4 g  = ((const float4*)gamma)[t];
    float4 be = ((const float4*)beta )[t];
    float4 o;
    o.x = (v.x - mean)*rstd*g.x + be.x;
    o.y = (v.y - mean)*rstd*g.y + be.y;
    o.z = (v.z - mean)*rstd*g.z + be.z;
    o.w = (v.w - mean)*rstd*g.w + be.w;
    ((float4*)(out + (size_t)row * ND))[t] = o;
}

// ---------------- launch ----------------
extern "C" void kernel_launch(void* const* d_in, const int* in_sizes, int n_in,
                              void* d_out, int out_size)
{
    const float* x   = (const float*)d_in[0];
    const float* rl  = (const float*)d_in[3];
    const float* qg  = (const float*)d_in[4];
    const float* kg  = (const float*)d_in[5];
    const float* vg  = (const float*)d_in[6];
    const float* tpb = (const float*)d_in[7];
    const float* pw  = (const float*)d_in[8];
    const float* pb  = (const float*)d_in[9];
    const float* ow  = (const float*)d_in[10];
    const float* ob  = (const float*)d_in[11];
    const float* hs  = (const float*)d_in[12];
    const float* lg  = (const float*)d_in[13];
    const float* lb  = (const float*)d_in[14];
    float* out = (float*)d_out;

    float *hp, *ymp, *zp;
    cudaGetSymbolAddress((void**)&hp,  g_h);
    cudaGetSymbolAddress((void**)&ymp, g_ym);
    cudaGetSymbolAddress((void**)&zp,  g_z);

    cudaFuncSetAttribute(gemm_mma<0>, cudaFuncAttributeMaxDynamicSharedMemorySize, G_SMEM_BYTES);
    cudaFuncSetAttribute(gemm_mma<1>, cudaFuncAttributeMaxDynamicSharedMemorySize, G_SMEM_BYTES);
    cudaFuncSetAttribute(attn_mma,    cudaFuncAttributeMaxDynamicSharedMemorySize, A_SMEM_BYTES);

    // 1. positions
    cumsum_kernel<<<NB, 1024>>>(rl);

    // 2. h = silu(x @ proj_w^T + proj_b)   [tf32 mma]
    gemm_mma<0><<<dim3(HID/128, MROWS/128), 256, G_SMEM_BYTES>>>(x, pw, pb, nullptr, hp, HID, ND);

    // 3. rope + gates -> fragment-major q/k/v (tf32 pre-rounded)
    rope_gate_kernel<<<(NB*NL*NH*32)/256, 256>>>(qg, kg, vg);

    // 4. fused attention + u-gate   [tf32 mma, LDS.128 fragment loads]
    attn_mma<<<dim3(NL/64, NB*NH), 256, A_SMEM_BYTES>>>(tpb, hs);

    // 5. z = ym @ out_w^T + out_b + x   [tf32 mma]
    gemm_mma<1><<<dim3(ND/128, MROWS/128), 256, G_SMEM_BYTES>>>(ymp, ow, ob, x, zp, ND, ND);

    // 6. layernorm
    ln_kernel<<<MROWS, 256>>>(zp, lg, lb, out);
}

// round 17
// speedup vs baseline: 1.6184x; 1.0133x over previous
#include <cuda_runtime.h>
#include <math.h>
#include <stdint.h>

#define NB 2
#define NL 2048
#define ND 1024
#define NH 16
#define NDH 64
#define MROWS (NB*NL)   // 4096
#define HID (4*ND)      // 4096

// ---------------- scratch ----------------
__device__ float g_h  [(size_t)MROWS * HID];
__device__ float g_q  [(size_t)NB*NH*NL*NDH];   // fragment-major
__device__ float g_k  [(size_t)NB*NH*NL*NDH];   // fragment-major
__device__ float g_v  [(size_t)NB*NH*NL*NDH];   // fragment-major
__device__ float g_ym [(size_t)MROWS * ND];
__device__ float g_z  [(size_t)MROWS * ND];
__device__ float g_pos[NB*NL];

__device__ __forceinline__ float silu_f(float x){
    return __fdividef(x, 1.0f + __expf(-x));
}

__device__ __forceinline__ uint32_t tf32_bits(float x){
    uint32_t u; asm("cvt.rna.tf32.f32 %0, %1;" : "=r"(u) : "f"(x));
    return u;
}
__device__ __forceinline__ float tf32_rnd(float x){ return __uint_as_float(tf32_bits(x)); }

__device__ __forceinline__ uint32_t smem_u32(const void* p){
    uint32_t a;
    asm("{ .reg .u64 t; cvta.to.shared.u64 t, %1; cvt.u32.u64 %0, t; }" : "=r"(a) : "l"(p));
    return a;
}
__device__ __forceinline__ void cp_async16(uint32_t saddr, const void* g){
    asm volatile("cp.async.cg.shared.global [%0], [%1], 16;" :: "r"(saddr), "l"(g));
}
#define CP_COMMIT()  asm volatile("cp.async.commit_group;" ::: "memory")
#define CP_WAIT(n)   asm volatile("cp.async.wait_group %0;" :: "n"(n) : "memory")

#define MMA16N8K8(c, a, b) \
    asm volatile("mma.sync.aligned.m16n8k8.row.col.f32.tf32.tf32.f32 " \
        "{%0,%1,%2,%3}, {%4,%5,%6,%7}, {%8,%9}, {%0,%1,%2,%3};" \
        : "+f"((c)[0]), "+f"((c)[1]), "+f"((c)[2]), "+f"((c)[3]) \
        : "r"((a)[0]), "r"((a)[1]), "r"((a)[2]), "r"((a)[3]), \
          "r"((b)[0]), "r"((b)[1]))

// ---------------- 1. cumsum of rope_lambda -> g_pos ----------------
__global__ void cumsum_kernel(const float* __restrict__ rl)
{
    __shared__ float s[1024];
    int b = blockIdx.x, t = threadIdx.x;
    const float* a = rl + (size_t)b * NL;
    float x0 = a[2*t], x1 = a[2*t+1];
    float sum = x0 + x1;
    s[t] = sum;
    __syncthreads();
    for (int off = 1; off < 1024; off <<= 1){
        float v = (t >= off) ? s[t-off] : 0.0f;
        __syncthreads();
        s[t] += v;
        __syncthreads();
    }
    float incl = s[t];
    g_pos[b*NL + 2*t]     = incl - x1;
    g_pos[b*NL + 2*t + 1] = incl;
}

// ---------------- 2/5. tf32 mma.sync GEMM (NT), 3-stage (unchanged) ----------------
#define GSTAGES 3
#define GKC 32
#define G_STRIDE 36
#define G_TILE_F (128*G_STRIDE)
#define G_TILE_B (G_TILE_F*4)
#define G_SMEM_BYTES (GSTAGES * 2 * G_TILE_B)   // 110592

template<int EPI>
__global__ void __launch_bounds__(256, 2)
gemm_mma(const float* __restrict__ A, const float* __restrict__ Bw,
         const float* __restrict__ bias, const float* __restrict__ resid,
         float* __restrict__ C, int N, int K)
{
    extern __shared__ float dsm[];
    const uint32_t sb = smem_u32(dsm);
    const int tid  = threadIdx.x;
    const int lane = tid & 31, wid = tid >> 5;
    const int wm = wid >> 2, wn = wid & 3;
    const int g  = lane >> 2, t = lane & 3;
    const int bn = blockIdx.x * 128;
    const int bm = blockIdx.y * 128;

    float acc[4][4][4];
    #pragma unroll
    for (int i = 0; i < 4; i++)
        #pragma unroll
        for (int j = 0; j < 4; j++)
            #pragma unroll
            for (int c = 0; c < 4; c++) acc[i][j][c] = 0.0f;

    auto load_stage = [&](int s, int kt){
        uint32_t base = sb + (uint32_t)s * (2*G_TILE_B);
        #pragma unroll
        for (int it = 0; it < 8; it++){
            int idx = tid + it*256;
            int isB = idx >> 10;
            int li  = idx & 1023;
            int row = li >> 3;
            int c16 = li & 7;
            const float* src = (isB ? (Bw + (size_t)(bn+row)*K)
                                    : (A  + (size_t)(bm+row)*K)) + kt + c16*4;
            cp_async16(base + (uint32_t)isB*G_TILE_B + (uint32_t)(row*144 + c16*16), src);
        }
        CP_COMMIT();
    };

    #pragma unroll
    for (int s = 0; s < GSTAGES; s++) load_stage(s, s*GKC);

    const int NCH = K / GKC;
    int s = 0;
    for (int ch = 0; ch < NCH; ch++){
        CP_WAIT(GSTAGES-1);
        __syncthreads();

        const float* As = dsm + (size_t)s*2*G_TILE_F;
        const float* Bs = As + G_TILE_F;
        const float* Awp = As + (wm*64 + g)*G_STRIDE + t;
        const float* Bwp = Bs + (wn*32 + g)*G_STRIDE + t;

        #pragma unroll
        for (int ks = 0; ks < 4; ks++){
            int k0 = ks*8;
            uint32_t b[4][2];
            #pragma unroll
            for (int fj = 0; fj < 4; fj++){
                const float* bp = Bwp + fj*8*G_STRIDE + k0;
                b[fj][0] = tf32_bits(bp[0]);
                b[fj][1] = tf32_bits(bp[4]);
            }
            #pragma unroll
            for (int fi = 0; fi < 4; fi++){
                const float* ap = Awp + fi*16*G_STRIDE + k0;
                uint32_t a[4];
                a[0] = tf32_bits(ap[0]);
                a[1] = tf32_bits(ap[8*G_STRIDE]);
                a[2] = tf32_bits(ap[4]);
                a[3] = tf32_bits(ap[8*G_STRIDE+4]);
                #pragma unroll
                for (int fj = 0; fj < 4; fj++)
                    MMA16N8K8(acc[fi][fj], a, b[fj]);
            }
        }
        __syncthreads();
        if (ch + GSTAGES < NCH) load_stage(s, (ch + GSTAGES)*GKC);
        if (++s == GSTAGES) s = 0;
    }

    #pragma unroll
    for (int fi = 0; fi < 4; fi++){
        int m0 = bm + wm*64 + fi*16 + g;
        #pragma unroll
        for (int fj = 0; fj < 4; fj++){
            int n = bn + wn*32 + fj*8 + 2*t;
            float2 bv = *(const float2*)(bias + n);
            float2 o0, o1;
            o0.x = acc[fi][fj][0] + bv.x; o0.y = acc[fi][fj][1] + bv.y;
            o1.x = acc[fi][fj][2] + bv.x; o1.y = acc[fi][fj][3] + bv.y;
            if (EPI == 0){
                o0.x = silu_f(o0.x); o0.y = silu_f(o0.y);
                o1.x = silu_f(o1.x); o1.y = silu_f(o1.y);
            } else {
                float2 r0 = *(const float2*)(resid + (size_t)m0*N + n);
                float2 r1 = *(const float2*)(resid + (size_t)(m0+8)*N + n);
                o0.x += r0.x; o0.y += r0.y;
                o1.x += r1.x; o1.y += r1.y;
            }
            *(float2*)(C + (size_t)m0*N + n)     = o0;
            *(float2*)(C + (size_t)(m0+8)*N + n) = o1;
        }
    }
}

// ---------------- fragment-major address helpers (as R16) ----------------
__device__ __forceinline__ size_t q_addr(int bh, int row, int dd){
    int rowblk = row >> 4;
    int ks = dd >> 3;
    int lane = ((row & 7) << 2) + (dd & 3);
    int slot = (((dd & 7) >> 2) << 1) + ((row & 15) >> 3);
    return ((size_t)bh*(NL>>4) + rowblk)*1024 + ks*128 + lane*4 + slot;
}
__device__ __forceinline__ size_t k_addr(int bh, int key, int dd){
    int jb = key >> 5;
    int kt = (key & 31) >> 3;
    int p  = dd >> 4;
    int lane = ((key & 7) << 2) + (dd & 3);
    int slot = (((dd >> 3) & 1) << 1) + ((dd & 7) >> 2);
    return ((size_t)bh*(NL>>5) + jb)*2048 + p*512 + kt*128 + lane*4 + slot;
}
__device__ __forceinline__ size_t v_addr(int bh, int key, int dd){
    int jb = key >> 5;
    int p  = (key & 31) >> 4;
    int nfg = dd >> 3;
    int lane = ((dd & 7) << 2) + (key & 3);
    int slot = (key & 15) >> 2;
    return ((size_t)bh*(NL>>5) + jb)*2048 + p*1024 + nfg*128 + lane*4 + slot;
}

// ---------------- 3. RoPE + gates -> fragment-major q/k/v ----------------
__global__ void rope_gate_kernel(const float* __restrict__ qg,
                                 const float* __restrict__ kg,
                                 const float* __restrict__ vg)
{
    int tid = blockIdx.x * blockDim.x + threadIdx.x;
    int d  = tid & 31;
    int hh = (tid >> 5) & 15;
    int l  = (tid >> 9) & 2047;
    int b  = tid >> 20;
    if (b >= NB) return;
    size_t row   = (size_t)b*NL + l;
    size_t hbase = row * HID;
    int bh = b*NH + hh;
    float p   = g_pos[row];
    float inv = expf(-(float)d * (9.210340371976184f / 32.0f));
    float fr  = p * inv;
    float sn, cs;
    sincosf(fr, &sn, &cs);
    {
        float2 e = *(const float2*)(&g_h[hbase + 2*ND + hh*NDH + 2*d]);
        float gq = qg[row*NH + hh];
        g_q[q_addr(bh, l, d)]      = tf32_rnd((e.x*cs - e.y*sn) * gq);
        g_q[q_addr(bh, l, d + 32)] = tf32_rnd((e.x*sn + e.y*cs) * gq);
    }
    {
        float2 e = *(const float2*)(&g_h[hbase + 3*ND + hh*NDH + 2*d]);
        float gk = kg[row*NH + hh];
        g_k[k_addr(bh, l, d)]      = tf32_rnd((e.x*cs - e.y*sn) * gk);
        g_k[k_addr(bh, l, d + 32)] = tf32_rnd((e.x*sn + e.y*cs) * gk);
    }
    {
        float gv = vg[row*NH + hh];
        g_v[v_addr(bh, l, d)]      = tf32_rnd(g_h[hbase + ND + hh*NDH + d]      * gv);
        g_v[v_addr(bh, l, d + 32)] = tf32_rnd(g_h[hbase + ND + hh*NDH + d + 32] * gv);
    }
}

// ---------------- 4. attn v6: ABK=64, warp-autonomous, no pair barrier ----------------
// CTA: 64 q-rows, 8 warps. Warp (rb,kh): rows rb*16..+15, keys kh*32..+31 of each
// 64-key block. QK (32 mma) -> epilogue -> warp-private S (A-frag packed, 2KB) ->
// syncwarp -> S@V over ALL 64 d (32 mma). kh partials of Y merged once at end.
// 3-slot KV ring (32KB/slot), ONE CTA barrier per 64 keys. smem 112KB -> 2 CTAs/SM.
#define A_SLOT_F 8192                      // K 2x2048 + V 2x2048 floats
#define A_QS_F 4096                        // Q region, reused as 8x512 warp S
#define A_SMEM_BYTES ((A_QS_F + 3*A_SLOT_F)*4)   // 114688

__global__ void __launch_bounds__(256, 2)
attn_mma(const float* __restrict__ bias, const float* __restrict__ head_scale)
{
    extern __shared__ float sm[];
    float* Qs = sm;                    // [4096] frag-major, reused as warp S
    float* KV = sm + A_QS_F;           // [3][K 4096 | V 4096]

    const int ib = (int)gridDim.x - 1 - (int)blockIdx.x;   // big tiles first
    const int bh = blockIdx.y;
    const int b  = bh >> 4, hh = bh & 15;
    const int tid = threadIdx.x, lane = tid & 31, wid = tid >> 5;
    const int g = lane >> 2, t = lane & 3;
    const int rb = wid >> 1, r0 = rb*16;
    const int kh = wid & 1;
    const int njb = ib + 1;                // 64-key blocks

    auto load_kv = [&](int slot, int jb){
        if (jb < njb){
            float* dst = KV + slot*A_SLOT_F;
            const float* srcK = g_k + ((size_t)bh*(NL>>5) + (size_t)jb*2)*2048;
            const float* srcV = g_v + ((size_t)bh*(NL>>5) + (size_t)jb*2)*2048;
            #pragma unroll
            for (int it = 0; it < 8; it++){
                int idx = tid + it*256;      // 0..2047 chunks
                int isV = idx >> 10;
                int li  = idx & 1023;
                const float* src = (isV ? srcV : srcK) + li*4;
                cp_async16(smem_u32(dst + isV*4096 + li*4), src);
            }
        }
        CP_COMMIT();
    };

    {   // group 0: Q tile (4096 floats, linear frag-major)
        const float* qp = g_q + ((size_t)bh*(NL>>4) + (size_t)ib*4)*1024;
        #pragma unroll
        for (int it = 0; it < 4; it++){
            int idx = tid + it*256;
            cp_async16(smem_u32(Qs + idx*4), qp + idx*4);
        }
        CP_COMMIT();
    }
    load_kv(0, 0);      // group 1
    load_kv(1, 1);      // group 2

    // hoist Q fragments (8 x LDS.128)
    CP_WAIT(2);
    __syncthreads();
    uint32_t Qa[8][4];
    #pragma unroll
    for (int ks = 0; ks < 8; ks++){
        float4 qv = *(const float4*)&Qs[rb*1024 + ks*128 + lane*4];
        Qa[ks][0] = __float_as_uint(qv.x);
        Qa[ks][1] = __float_as_uint(qv.y);
        Qa[ks][2] = __float_as_uint(qv.z);
        Qa[ks][3] = __float_as_uint(qv.w);
    }
    __syncthreads();    // Q reads done before S region reuse (pair shares region)

    const float scale = head_scale[hh];
    float Yc[8][4];
    #pragma unroll
    for (int j = 0; j < 8; j++)
        #pragma unroll
        for (int c = 0; c < 4; c++) Yc[j][c] = 0.0f;

    const int ig0 = ib*64 + r0 + g;
    float* Sw = Qs + wid*512;           // warp-private S: [ks(4)][lane(32)][slot(4)]
    const int hi2   = (t >> 1) * 2;     // slot base for this thread's key cols
    const int lane0 = g*4 + ((2*t)   & 3);
    const int lane1 = g*4 + ((2*t+1) & 3);

    for (int jb = 0; jb < njb; ++jb){
        int slot = jb % 3;
        CP_WAIT(1);                        // slot jb%3 arrived
        __syncthreads();                   // prev iter fully done (overwrite-safe)
        load_kv((jb + 2) % 3, jb + 2);     // refill (empty commit if beyond)

        // bias prefetch (hidden under QK mmas)
        float2 pb0[4], pb1[4];
        {
            const float* bp = bias + ((size_t)b*NL + ig0)*NL + jb*64 + kh*32 + 2*t;
            #pragma unroll
            for (int nf = 0; nf < 4; nf++){
                pb0[nf] = *(const float2*)(bp + nf*8);
                pb1[nf] = *(const float2*)(bp + nf*8 + (size_t)8*NL);
            }
        }

        const float* Ksb = KV + slot*A_SLOT_F + kh*2048;
        const float* Vsb = KV + slot*A_SLOT_F + 4096 + kh*2048;

        // ---- S = Q @ K^T : 16 rows x 32 keys (warp-private) ----
        float Sc[4][4];
        #pragma unroll
        for (int nf = 0; nf < 4; nf++)
            #pragma unroll
            for (int c = 0; c < 4; c++) Sc[nf][c] = 0.0f;

        #pragma unroll
        for (int p = 0; p < 4; p++){
            #pragma unroll
            for (int kt = 0; kt < 4; kt++){
                float4 kf = *(const float4*)&Ksb[p*512 + kt*128 + lane*4];
                uint32_t bf[2];
                bf[0] = __float_as_uint(kf.x); bf[1] = __float_as_uint(kf.y);
                MMA16N8K8(Sc[kt], Qa[2*p], bf);
                bf[0] = __float_as_uint(kf.z); bf[1] = __float_as_uint(kf.w);
                MMA16N8K8(Sc[kt], Qa[2*p+1], bf);
            }
        }

        // ---- epilogue: scale + 4*bias + silu + causal -> Sw (A-frag packed) ----
        #pragma unroll
        for (int nf = 0; nf < 4; nf++){
            int jg = jb*64 + kh*32 + nf*8 + 2*t;
            float z00 = silu_f(fmaf(Sc[nf][0], scale, 4.0f*pb0[nf].x));
            float z01 = silu_f(fmaf(Sc[nf][1], scale, 4.0f*pb0[nf].y));
            float z10 = silu_f(fmaf(Sc[nf][2], scale, 4.0f*pb1[nf].x));
            float z11 = silu_f(fmaf(Sc[nf][3], scale, 4.0f*pb1[nf].y));
            if (jg     > ig0    ) z00 = 0.0f;
            if (jg + 1 > ig0    ) z01 = 0.0f;
            if (jg     > ig0 + 8) z10 = 0.0f;
            if (jg + 1 > ig0 + 8) z11 = 0.0f;
            float2 s0, s1;
            s0.x = tf32_rnd(z00); s0.y = tf32_rnd(z10);
            s1.x = tf32_rnd(z01); s1.y = tf32_rnd(z11);
            *(float2*)&Sw[nf*128 + lane0*4 + hi2] = s0;   // (row g, row g+8) @ key 2t
            *(float2*)&Sw[nf*128 + lane1*4 + hi2] = s1;   // @ key 2t+1
        }
        __syncwarp();

        // ---- Y += S @ V : 16 rows x 64 d over this warp's 32 keys ----
        #pragma unroll
        for (int p = 0; p < 2; p++){
            float4 a0v = *(const float4*)&Sw[(2*p)*128 + lane*4];
            float4 a1v = *(const float4*)&Sw[(2*p+1)*128 + lane*4];
            uint32_t A0[4], A1[4];
            A0[0]=__float_as_uint(a0v.x); A0[1]=__float_as_uint(a0v.y);
            A0[2]=__float_as_uint(a0v.z); A0[3]=__float_as_uint(a0v.w);
            A1[0]=__float_as_uint(a1v.x); A1[1]=__float_as_uint(a1v.y);
            A1[2]=__float_as_uint(a1v.z); A1[3]=__float_as_uint(a1v.w);
            #pragma unroll
            for (int nfg = 0; nfg < 8; nfg++){
                float4 vf = *(const float4*)&Vsb[p*1024 + nfg*128 + lane*4];
                uint32_t bf[2];
                bf[0] = __float_as_uint(vf.x); bf[1] = __float_as_uint(vf.y);
                MMA16N8K8(Yc[nfg], A0, bf);
                bf[0] = __float_as_uint(vf.z); bf[1] = __float_as_uint(vf.w);
                MMA16N8K8(Yc[nfg], A1, bf);
            }
        }
        __syncwarp();   // SV reads done before next iter's Sw overwrite
    }

    // ---- merge kh partials + u-gate + store ----
    __syncthreads();                       // all KV-slot readers done (reuse as scratch)
    float* red = KV + rb*1024;             // per-rb 4KB scratch
    if (kh == 1){
        #pragma unroll
        for (int nfg = 0; nfg < 8; nfg++){
            float4 v;
            v.x = Yc[nfg][0]; v.y = Yc[nfg][1];
            v.z = Yc[nfg][2]; v.w = Yc[nfg][3];
            *(float4*)&red[nfg*128 + lane*4] = v;
        }
    }
    __syncthreads();
    if (kh == 0){
        int l = ib*64 + r0 + g;
        size_t row0 = (size_t)b*NL + l;
        #pragma unroll
        for (int nfg = 0; nfg < 8; nfg++){
            float4 pv = *(const float4*)&red[nfg*128 + lane*4];
            int d0 = nfg*8 + 2*t;
            float2 u0 = *(const float2*)&g_h[row0*HID + hh*NDH + d0];
            float2 u1 = *(const float2*)&g_h[(row0+8)*HID + hh*NDH + d0];
            float2 o0, o1;
            o0.x = (Yc[nfg][0] + pv.x)*u0.x; o0.y = (Yc[nfg][1] + pv.y)*u0.y;
            o1.x = (Yc[nfg][2] + pv.z)*u1.x; o1.y = (Yc[nfg][3] + pv.w)*u1.y;
            *(float2*)&g_ym[row0*ND + hh*NDH + d0]     = o0;
            *(float2*)&g_ym[(row0+8)*ND + hh*NDH + d0] = o1;
        }
    }
}

// ---------------- 6. LayerNorm ----------------
__global__ void ln_kernel(const float* __restrict__ z, const float* __restrict__ gamma,
                          const float* __restrict__ beta, float* __restrict__ out)
{
    __shared__ float rs[8], rq[8], mv[2];
    int row = blockIdx.x;
    int t = threadIdx.x;
    const float4* zr = (const float4*)(z + (size_t)row * ND);
    float4 v = zr[t];
    float s  = v.x + v.y + v.z + v.w;
    float sq = v.x*v.x + v.y*v.y + v.z*v.z + v.w*v.w;
    #pragma unroll
    for (int o = 16; o; o >>= 1){
        s  += __shfl_down_sync(0xffffffffu, s,  o);
        sq += __shfl_down_sync(0xffffffffu, sq, o);
    }
    if ((t & 31) == 0){ rs[t>>5] = s; rq[t>>5] = sq; }
    __syncthreads();
    if (t == 0){
        float S = 0.f, Q = 0.f;
        #pragma unroll
        for (int i = 0; i < 8; i++){ S += rs[i]; Q += rq[i]; }
        float mean = S * (1.0f/ND);
        float var  = Q * (1.0f/ND) - mean*mean;
        mv[0] = mean; mv[1] = rsqrtf(var + 1e-5f);
    }
    __syncthreads();
    float mean = mv[0], rstd = mv[1];
    float4 g  = ((const float4*)gamma)[t];
    float4 be = ((const float4*)beta )[t];
    float4 o;
    o.x = (v.x - mean)*rstd*g.x + be.x;
    o.y = (v.y - mean)*rstd*g.y + be.y;
    o.z = (v.z - mean)*rstd*g.z + be.z;
    o.w = (v.w - mean)*rstd*g.w + be.w;
    ((float4*)(out + (size_t)row * ND))[t] = o;
}

// ---------------- launch ----------------
extern "C" void kernel_launch(void* const* d_in, const int* in_sizes, int n_in,
                              void* d_out, int out_size)
{
    const float* x   = (const float*)d_in[0];
    const float* rl  = (const float*)d_in[3];
    const float* qg  = (const float*)d_in[4];
    const float* kg  = (const float*)d_in[5];
    const float* vg  = (const float*)d_in[6];
    const float* tpb = (const float*)d_in[7];
    const float* pw  = (const float*)d_in[8];
    const float* pb  = (const float*)d_in[9];
    const float* ow  = (const float*)d_in[10];
    const float* ob  = (const float*)d_in[11];
    const float* hs  = (const float*)d_in[12];
    const float* lg  = (const float*)d_in[13];
    const float* lb  = (const float*)d_in[14];
    float* out = (float*)d_out;

    float *hp, *ymp, *zp;
    cudaGetSymbolAddress((void**)&hp,  g_h);
    cudaGetSymbolAddress((void**)&ymp, g_ym);
    cudaGetSymbolAddress((void**)&zp,  g_z);

    cudaFuncSetAttribute(gemm_mma<0>, cudaFuncAttributeMaxDynamicSharedMemorySize, G_SMEM_BYTES);
    cudaFuncSetAttribute(gemm_mma<1>, cudaFuncAttributeMaxDynamicSharedMemorySize, G_SMEM_BYTES);
    cudaFuncSetAttribute(attn_mma,    cudaFuncAttributeMaxDynamicSharedMemorySize, A_SMEM_BYTES);

    // 1. positions
    cumsum_kernel<<<NB, 1024>>>(rl);

    // 2. h = silu(x @ proj_w^T + proj_b)   [tf32 mma]
    gemm_mma<0><<<dim3(HID/128, MROWS/128), 256, G_SMEM_BYTES>>>(x, pw, pb, nullptr, hp, HID, ND);

    // 3. rope + gates -> fragment-major q/k/v
    rope_gate_kernel<<<(NB*NL*NH*32)/256, 256>>>(qg, kg, vg);

    // 4. fused attention + u-gate   [tf32 mma, warp-autonomous]
    attn_mma<<<dim3(NL/64, NB*NH), 256, A_SMEM_BYTES>>>(tpb, hs);

    // 5. z = ym @ out_w^T + out_b + x   [tf32 mma]
    gemm_mma<1><<<dim3(ND/128, MROWS/128), 256, G_SMEM_BYTES>>>(ymp, ow, ob, x, zp, ND, ND);

    // 6. layernorm
    ln_kernel<<<MROWS, 256>>>(zp, lg, lb, out);
}